// round 5
// baseline (speedup 1.0000x reference)
#include <cuda_runtime.h>

#define NQ      12
#define NT      512         // threads per CTA
#define NR      8           // amplitudes per thread
#define NLAYERS 4
#define NGATES  60          // 12 encoding + 48 Rot
#define XP      9           // padded row pitch (u64): conflict-free transposes

typedef unsigned long long u64;

// ---- packed f32x2 helpers (re in lo 32 bits, im in hi 32 bits) ----
__device__ __forceinline__ u64 pack2(float lo, float hi) {
    u64 r; asm("mov.b64 %0, {%1, %2};" : "=l"(r) : "f"(lo), "f"(hi)); return r;
}
__device__ __forceinline__ void unpack2(u64 v, float& lo, float& hi) {
    asm("mov.b64 {%0, %1}, %2;" : "=f"(lo), "=f"(hi) : "l"(v));
}
__device__ __forceinline__ u64 swap2(u64 v) {
    u64 r;
    asm("{\n\t.reg .b32 l, h;\n\tmov.b64 {l, h}, %1;\n\tmov.b64 %0, {h, l};\n\t}"
        : "=l"(r) : "l"(v));
    return r;
}
__device__ __forceinline__ u64 ffma2(u64 a, u64 b, u64 c) {
    u64 r; asm("fma.rn.f32x2 %0, %1, %2, %3;" : "=l"(r) : "l"(a), "l"(b), "l"(c)); return r;
}
__device__ __forceinline__ u64 fmul2(u64 a, u64 b) {
    u64 r; asm("mul.rn.f32x2 %0, %1, %2;" : "=l"(r) : "l"(a), "l"(b)); return r;
}

// Gate coefficients per gate (8 u64): [A00 B00 A01 B01 A10 B10 A11 B11]
// A(c)=(re,re), B(c)=(-im,im): complex mul c*m = A*m + B*swap(m).

// ---- gate on register bit P (P in 0..2): pure register FMA ----
template<int P>
__device__ __forceinline__ void gate_reg(u64* st, const u64* g) {
    ulonglong2 cA = *(const ulonglong2*)(g + 0);   // A00, B00
    ulonglong2 cB = *(const ulonglong2*)(g + 2);   // A01, B01
    ulonglong2 cC = *(const ulonglong2*)(g + 4);   // A10, B10
    ulonglong2 cD = *(const ulonglong2*)(g + 6);   // A11, B11
#pragma unroll
    for (int k = 0; k < NR / 2; k++) {
        const int r0 = ((k >> P) << (P + 1)) | (k & ((1 << P) - 1));
        const int r1 = r0 | (1 << P);
        u64 m0 = st[r0], m1 = st[r1];
        u64 s0 = swap2(m0), s1 = swap2(m1);
        st[r0] = ffma2(cB.x, m1, ffma2(cB.y, s1, ffma2(cA.y, s0, fmul2(cA.x, m0))));
        st[r1] = ffma2(cD.x, m1, ffma2(cD.y, s1, ffma2(cC.y, s0, fmul2(cC.x, m0))));
    }
}

// ======================= layouts =======================
// amp index bits idx[11:0]; thread bits t8..t0; register bits r2..r0.
// phys(idx) = (idx>>3)*XP + (idx&7)
// Layout A: reg = idx[2:0]   (wires 9,10,11)  thread = idx[11:3]
// Layout B: reg = idx[5:3]   (wires 6,7,8)
// Layout C: reg = idx[8:6]   (wires 3,4,5)
// Layout D: reg = idx[11:9]  (wires 0,1,2)    thread = idx[8:0]
// Address patterns (row*XP + col):
//   A: row = t,                                   col = r   (contig per thread)
//   B: row = ((t>>3)<<3)|r,                       col = t&7
//   C: row = ((t>>6)<<6)|(r<<3)|((t>>3)&7),       col = t&7
//   D: row = (r<<6)|(t>>3),                       col = t&7

#define ADDR_A(t, r) ((t) * XP + (r))
#define ADDR_B(t, r) (((((t) >> 3) << 3) | (r)) * XP + ((t) & 7))
#define ADDR_C(t, r) (((((t) >> 6) << 6) | ((r) << 3) | (((t) >> 3) & 7)) * XP + ((t) & 7))
#define ADDR_D(t, r) ((((r) << 6) | ((t) >> 3)) * XP + ((t) & 7))

// A<->B is warp-local (rows (t&~7)|r stay inside the 8-thread group / warp).
__device__ __forceinline__ void exch_A_to_B(u64* st, int t, u64* x) {
#pragma unroll
    for (int r = 0; r < NR; r++) x[ADDR_A(t, r)] = st[r];
    __syncwarp();
#pragma unroll
    for (int r = 0; r < NR; r++) st[r] = x[ADDR_B(t, r)];
    __syncwarp();
}
__device__ __forceinline__ void exch_B_to_A(u64* st, int t, u64* x) {
#pragma unroll
    for (int r = 0; r < NR; r++) x[ADDR_B(t, r)] = st[r];
    __syncwarp();
#pragma unroll
    for (int r = 0; r < NR; r++) st[r] = x[ADDR_A(t, r)];
    __syncwarp();
}
__device__ __forceinline__ void exch_B_to_C(u64* st, int t, u64* x) {
#pragma unroll
    for (int r = 0; r < NR; r++) x[ADDR_B(t, r)] = st[r];
    __syncthreads();
#pragma unroll
    for (int r = 0; r < NR; r++) st[r] = x[ADDR_C(t, r)];
    __syncthreads();
}
__device__ __forceinline__ void exch_C_to_B(u64* st, int t, u64* x) {
#pragma unroll
    for (int r = 0; r < NR; r++) x[ADDR_C(t, r)] = st[r];
    __syncthreads();
#pragma unroll
    for (int r = 0; r < NR; r++) st[r] = x[ADDR_B(t, r)];
    __syncthreads();
}
__device__ __forceinline__ void exch_C_to_D(u64* st, int t, u64* x) {
#pragma unroll
    for (int r = 0; r < NR; r++) x[ADDR_C(t, r)] = st[r];
    __syncthreads();
#pragma unroll
    for (int r = 0; r < NR; r++) st[r] = x[ADDR_D(t, r)];
    __syncthreads();
}
__device__ __forceinline__ void exch_D_to_C(u64* st, int t, u64* x) {
#pragma unroll
    for (int r = 0; r < NR; r++) x[ADDR_D(t, r)] = st[r];
    __syncthreads();
#pragma unroll
    for (int r = 0; r < NR; r++) st[r] = x[ADDR_C(t, r)];
    __syncthreads();
}

// ======================= sweeps =======================
// gates for wire q at G + q*8. Within each layout, smallest wire -> reg bit 2.
__device__ __forceinline__ void sweep_A_to_D(u64* st, const u64* G, int t, u64* x) {
    gate_reg<2>(st, G +  9 * 8);  gate_reg<1>(st, G + 10 * 8);  gate_reg<0>(st, G + 11 * 8);
    exch_A_to_B(st, t, x);
    gate_reg<2>(st, G +  6 * 8);  gate_reg<1>(st, G +  7 * 8);  gate_reg<0>(st, G +  8 * 8);
    exch_B_to_C(st, t, x);
    gate_reg<2>(st, G +  3 * 8);  gate_reg<1>(st, G +  4 * 8);  gate_reg<0>(st, G +  5 * 8);
    exch_C_to_D(st, t, x);
    gate_reg<2>(st, G +  0 * 8);  gate_reg<1>(st, G +  1 * 8);  gate_reg<0>(st, G +  2 * 8);
}
__device__ __forceinline__ void sweep_D_to_A(u64* st, const u64* G, int t, u64* x) {
    gate_reg<2>(st, G +  0 * 8);  gate_reg<1>(st, G +  1 * 8);  gate_reg<0>(st, G +  2 * 8);
    exch_D_to_C(st, t, x);
    gate_reg<2>(st, G +  3 * 8);  gate_reg<1>(st, G +  4 * 8);  gate_reg<0>(st, G +  5 * 8);
    exch_C_to_B(st, t, x);
    gate_reg<2>(st, G +  6 * 8);  gate_reg<1>(st, G +  7 * 8);  gate_reg<0>(st, G +  8 * 8);
    exch_B_to_A(st, t, x);
    gate_reg<2>(st, G +  9 * 8);  gate_reg<1>(st, G + 10 * 8);  gate_reg<0>(st, G + 11 * 8);
}

// ======================= CNOT primitives =======================
template<int PC, int PT>
__device__ __forceinline__ void cnot_reg_rc(u64* st) {
#pragma unroll
    for (int r = 0; r < NR; r++) {
        if (((r >> PC) & 1) == 1 && ((r >> PT) & 1) == 0) {
            u64 tmp = st[r]; st[r] = st[r | (1 << PT)]; st[r | (1 << PT)] = tmp;
        }
    }
}
template<int PT>
__device__ __forceinline__ void cnot_reg_uc(u64* st, bool ctrl) {
    if (ctrl) {
#pragma unroll
        for (int r = 0; r < NR; r++) {
            if (((r >> PT) & 1) == 0) {
                u64 tmp = st[r]; st[r] = st[r | (1 << PT)]; st[r | (1 << PT)] = tmp;
            }
        }
    }
}
template<int X>
__device__ __forceinline__ void cnot_lane(u64* st, bool ctrl) {
#pragma unroll
    for (int r = 0; r < NR; r++) {
        u64 o = __shfl_xor_sync(0xFFFFFFFFu, st[r], X);
        if (ctrl) st[r] = o;
    }
}
// ctrl = thread-bit predicate (uniform between partners), target = thread bit (t^X)
template<int X>
__device__ __forceinline__ void cnot_cross(u64* st, int t, bool ctrl, u64* x) {
    if (ctrl) {
#pragma unroll
        for (int r = 0; r < NR; r++) x[ADDR_A(t, r)] = st[r];
    }
    __syncthreads();
    if (ctrl) {
        const int p = t ^ X;
#pragma unroll
        for (int r = 0; r < NR; r++) st[r] = x[ADDR_A(p, r)];
    }
    __syncthreads();
}
// ctrl = reg bit 0 (odd r), target = thread bit 8 (t^256)
__device__ __forceinline__ void cnot_regctrl_t8(u64* st, int t, u64* x) {
#pragma unroll
    for (int r = 1; r < NR; r += 2) x[ADDR_A(t, r)] = st[r];
    __syncthreads();
    const int p = t ^ 256;
#pragma unroll
    for (int r = 1; r < NR; r += 2) st[r] = x[ADDR_A(p, r)];
    __syncthreads();
}

__global__ void __launch_bounds__(NT)
qsim_kernel(const float* __restrict__ x,       // (B, 12)
            const float* __restrict__ w,       // (4, 12, 3)
            const float* __restrict__ ent,     // (4, 12)
            float* __restrict__ out)           // (B, 12)
{
    __shared__ __align__(16) u64 Usm[NGATES * 8];   // 3840 B gate coefficients
    __shared__ u64   xbuf[NT * XP];                 // 36864 B padded exchange buffer
    __shared__ float red[(NT / 32) * NQ];

    const int b    = blockIdx.x;
    const int t    = threadIdx.x;
    const int lane = t & 31;

    // ---- precompute all 60 gate matrices (one thread per gate) ----
    if (t < NGATES) {
        const float PI = 3.14159265358979323846f;
        float2 u00, u01, u10, u11;
        if (t < NQ) {
            float xv = __ldg(&x[b * NQ + t]);
            float s, c;  sincosf(0.5f * PI * xv, &s, &c);
            float sh, ch; sincosf(0.5f * PI * xv * xv, &sh, &ch);
            u00 = make_float2( c * ch, -c * sh);
            u01 = make_float2(-s * ch,  s * sh);
            u10 = make_float2( s * ch,  s * sh);
            u11 = make_float2( c * ch,  c * sh);
        } else {
            int gi = t - NQ;   // = l*12 + q
            float phi = __ldg(&w[gi * 3 + 0]);
            float th  = __ldg(&w[gi * 3 + 1]);
            float om  = __ldg(&w[gi * 3 + 2]);
            float s, c;  sincosf(0.5f * th, &s, &c);
            float sp, cp; sincosf(0.5f * (om + phi), &sp, &cp);
            float sm, cm; sincosf(0.5f * (om - phi), &sm, &cm);
            u00 = make_float2( c * cp, -c * sp);
            u01 = make_float2(-s * cm,  s * sm);
            u10 = make_float2( s * cm,  s * sm);
            u11 = make_float2( c * cp,  c * sp);
        }
        u64* g = &Usm[t * 8];
        g[0] = pack2(u00.x, u00.x);  g[1] = pack2(-u00.y, u00.y);
        g[2] = pack2(u01.x, u01.x);  g[3] = pack2(-u01.y, u01.y);
        g[4] = pack2(u10.x, u10.x);  g[5] = pack2(-u10.y, u10.y);
        g[6] = pack2(u11.x, u11.x);  g[7] = pack2(-u11.y, u11.y);
    }
    __syncthreads();

    // ---- register-resident state, layout A: amp (t<<3)|r in st[r] ----
    u64 st[NR];
#pragma unroll
    for (int r = 0; r < NR; r++) st[r] = 0ULL;
    if (t == 0) st[0] = pack2(1.0f, 0.0f);

    // encoding sweep: A -> D
    sweep_A_to_D(st, Usm, t, xbuf);

    // variational layers: l=0 D->A (CNOTs in A), l=1 A->D (CNOTs in D), ...
    for (int l = 0; l < NLAYERS; l++) {
        const u64* G = &Usm[(NQ + l * NQ) * 8];
        const float* el = &ent[l * NQ];
        if ((l & 1) == 0) {
            sweep_D_to_A(st, G, t, xbuf);
            // Layout A: w0..w8 = t8..t0 ; w9,w10,w11 = r2,r1,r0
            if (__ldg(&el[0])  > 0.5f) cnot_cross<128>(st, t, (t >> 8) & 1, xbuf); // c=t8,t=t7
            if (__ldg(&el[1])  > 0.5f) cnot_cross<64>(st, t, (t >> 7) & 1, xbuf);  // c=t7,t=t6
            if (__ldg(&el[2])  > 0.5f) cnot_cross<32>(st, t, (t >> 6) & 1, xbuf);  // c=t6,t=t5
            if (__ldg(&el[3])  > 0.5f) cnot_lane<16>(st, (t >> 5) & 1);            // c=t5,t=t4
            if (__ldg(&el[4])  > 0.5f) cnot_lane<8>(st, (lane >> 4) & 1);          // c=t4,t=t3
            if (__ldg(&el[5])  > 0.5f) cnot_lane<4>(st, (lane >> 3) & 1);          // c=t3,t=t2
            if (__ldg(&el[6])  > 0.5f) cnot_lane<2>(st, (lane >> 2) & 1);          // c=t2,t=t1
            if (__ldg(&el[7])  > 0.5f) cnot_lane<1>(st, (lane >> 1) & 1);          // c=t1,t=t0
            if (__ldg(&el[8])  > 0.5f) cnot_reg_uc<2>(st, lane & 1);               // c=t0,t=r2
            if (__ldg(&el[9])  > 0.5f) cnot_reg_rc<2, 1>(st);                      // c=r2,t=r1
            if (__ldg(&el[10]) > 0.5f) cnot_reg_rc<1, 0>(st);                      // c=r1,t=r0
            if (__ldg(&el[11]) > 0.5f) cnot_regctrl_t8(st, t, xbuf);               // c=r0,t=t8
        } else {
            sweep_A_to_D(st, G, t, xbuf);
            // Layout D: w0,w1,w2 = r2,r1,r0 ; w3..w11 = t8..t0
            if (__ldg(&el[0])  > 0.5f) cnot_reg_rc<2, 1>(st);                      // c=r2,t=r1
            if (__ldg(&el[1])  > 0.5f) cnot_reg_rc<1, 0>(st);                      // c=r1,t=r0
            if (__ldg(&el[2])  > 0.5f) cnot_regctrl_t8(st, t, xbuf);               // c=r0,t=t8
            if (__ldg(&el[3])  > 0.5f) cnot_cross<128>(st, t, (t >> 8) & 1, xbuf); // c=t8,t=t7
            if (__ldg(&el[4])  > 0.5f) cnot_cross<64>(st, t, (t >> 7) & 1, xbuf);  // c=t7,t=t6
            if (__ldg(&el[5])  > 0.5f) cnot_cross<32>(st, t, (t >> 6) & 1, xbuf);  // c=t6,t=t5
            if (__ldg(&el[6])  > 0.5f) cnot_lane<16>(st, (t >> 5) & 1);            // c=t5,t=t4
            if (__ldg(&el[7])  > 0.5f) cnot_lane<8>(st, (lane >> 4) & 1);          // c=t4,t=t3
            if (__ldg(&el[8])  > 0.5f) cnot_lane<4>(st, (lane >> 3) & 1);          // c=t3,t=t2
            if (__ldg(&el[9])  > 0.5f) cnot_lane<2>(st, (lane >> 2) & 1);          // c=t2,t=t1
            if (__ldg(&el[10]) > 0.5f) cnot_lane<1>(st, (lane >> 1) & 1);          // c=t1,t=t0
            if (__ldg(&el[11]) > 0.5f) cnot_reg_uc<2>(st, lane & 1);               // c=t0,t=r2
        }
    }
    // final layout: D (w0,w1,w2 = r2,r1,r0 ; w3..w11 = t8..t0)

    // ---- readout: <Z_q> ----
    float psum = 0.f, a0 = 0.f, a1 = 0.f, a2 = 0.f;
#pragma unroll
    for (int r = 0; r < NR; r++) {
        float re, im; unpack2(st[r], re, im);
        float p = re * re + im * im;
        psum += p;
        a0 += (r & 4) ? -p : p;   // w0 = r2
        a1 += (r & 2) ? -p : p;   // w1 = r1
        a2 += (r & 1) ? -p : p;   // w2 = r0
    }
    float acc[NQ];
    acc[0] = a0; acc[1] = a1; acc[2] = a2;
#pragma unroll
    for (int q = 3; q < NQ; q++)               // wires 3..11 -> thread bits t8..t0
        acc[q] = ((t >> (11 - q)) & 1) ? -psum : psum;

    const int wid = t >> 5;
#pragma unroll
    for (int q = 0; q < NQ; q++) {
        float v = acc[q];
#pragma unroll
        for (int o = 16; o; o >>= 1) v += __shfl_xor_sync(0xFFFFFFFFu, v, o);
        if (lane == 0) red[wid * NQ + q] = v;
    }
    __syncthreads();

    if (t < NQ) {
        float s = 0.f;
#pragma unroll
        for (int wi = 0; wi < NT / 32; wi++) s += red[wi * NQ + t];
        out[b * NQ + t] = s;   // SCALE = 1
    }
}

extern "C" void kernel_launch(void* const* d_in, const int* in_sizes, int n_in,
                              void* d_out, int out_size)
{
    const float* x   = (const float*)d_in[0];   // (B, 12)
    const float* w   = (const float*)d_in[1];   // (4, 12, 3)
    const float* ent = (const float*)d_in[2];   // (4, 12)
    float* out = (float*)d_out;                 // (B, 12)

    int B = in_sizes[0] / NQ;
    qsim_kernel<<<B, NT>>>(x, w, ent, out);
}

// round 6
// speedup vs baseline: 1.2433x; 1.2433x over previous
#include <cuda_runtime.h>

#define NQ      12
#define NT      256         // threads per CTA
#define NR      16          // amplitudes per thread
#define NLAYERS 4
#define NGATES  60          // 12 encoding + 48 Rot
#define XP      17          // padded row pitch (u64) -> conflict-free transposes

typedef unsigned long long u64;

// ---- packed f32x2 helpers (re in lo 32 bits, im in hi 32 bits) ----
__device__ __forceinline__ u64 pack2(float lo, float hi) {
    u64 r; asm("mov.b64 %0, {%1, %2};" : "=l"(r) : "f"(lo), "f"(hi)); return r;
}
__device__ __forceinline__ void unpack2(u64 v, float& lo, float& hi) {
    asm("mov.b64 {%0, %1}, %2;" : "=f"(lo), "=f"(hi) : "l"(v));
}
__device__ __forceinline__ u64 swap2(u64 v) {
    u64 r;
    asm("{\n\t.reg .b32 l, h;\n\tmov.b64 {l, h}, %1;\n\tmov.b64 %0, {h, l};\n\t}"
        : "=l"(r) : "l"(v));
    return r;
}
__device__ __forceinline__ u64 ffma2(u64 a, u64 b, u64 c) {
    u64 r; asm("fma.rn.f32x2 %0, %1, %2, %3;" : "=l"(r) : "l"(a), "l"(b), "l"(c)); return r;
}
__device__ __forceinline__ u64 fmul2(u64 a, u64 b) {
    u64 r; asm("mul.rn.f32x2 %0, %1, %2;" : "=l"(r) : "l"(a), "l"(b)); return r;
}

// Gate coefficients per gate (8 u64): [A00 B00 A01 B01 A10 B10 A11 B11]
// A(c)=(re,re), B(c)=(-im,im): complex mul c*m = A*m + B*swap(m).

// ---- gate on register bit P: pure register FMA ----
template<int P>
__device__ __forceinline__ void gate_reg(u64* st, const u64* g) {
    ulonglong2 cA = *(const ulonglong2*)(g + 0);   // A00, B00
    ulonglong2 cB = *(const ulonglong2*)(g + 2);   // A01, B01
    ulonglong2 cC = *(const ulonglong2*)(g + 4);   // A10, B10
    ulonglong2 cD = *(const ulonglong2*)(g + 6);   // A11, B11
#pragma unroll
    for (int k = 0; k < NR / 2; k++) {
        const int r0 = ((k >> P) << (P + 1)) | (k & ((1 << P) - 1));
        const int r1 = r0 | (1 << P);
        u64 m0 = st[r0], m1 = st[r1];
        u64 s0 = swap2(m0), s1 = swap2(m1);
        st[r0] = ffma2(cB.x, m1, ffma2(cB.y, s1, ffma2(cA.y, s0, fmul2(cA.x, m0))));
        st[r1] = ffma2(cD.x, m1, ffma2(cD.y, s1, ffma2(cC.y, s0, fmul2(cC.x, m0))));
    }
}

// ======================= layouts & transposes =======================
// amp index n[11:0], wire q <-> bit (11-q). phys(n) = (n>>4)*XP + (n&15) = n + (n>>4).
// Layout A: n = (t<<4)|r                       wires 0..7 = t7..t0, 8..11 = r3..r0
// Layout C: n = ((t>>4)<<8)|(r<<4)|(t&15)      wires 0..3 = t7..t4, 4..7 = r3..r0, 8..11 = t3..t0
// Layout D: n = (r<<8)|t                       wires 0..3 = r3..r0, 4..11 = t7..t0

#define ADDR_A(t, r) ((t) * XP + (r))
#define ADDR_C(t, r) (((((t) >> 4) << 4) | (r)) * XP + ((t) & 15))
#define ADDR_D(t, r) ((((r) << 4) | ((t) >> 4)) * XP + ((t) & 15))

// A->C: warp-local (swaps lane bits with reg bits)
__device__ __forceinline__ void exch_A_to_C(u64* st, int t, u64* xbuf) {
#pragma unroll
    for (int r = 0; r < NR; r++) xbuf[ADDR_A(t, r)] = st[r];
    __syncwarp();
#pragma unroll
    for (int r = 0; r < NR; r++) st[r] = xbuf[ADDR_C(t, r)];
    __syncwarp();
}
__device__ __forceinline__ void exch_C_to_A(u64* st, int t, u64* xbuf) {
#pragma unroll
    for (int r = 0; r < NR; r++) xbuf[ADDR_C(t, r)] = st[r];
    __syncwarp();
#pragma unroll
    for (int r = 0; r < NR; r++) st[r] = xbuf[ADDR_A(t, r)];
    __syncwarp();
}
__device__ __forceinline__ void exch_C_to_D(u64* st, int t, u64* xbuf) {
#pragma unroll
    for (int r = 0; r < NR; r++) xbuf[ADDR_C(t, r)] = st[r];
    __syncthreads();
#pragma unroll
    for (int r = 0; r < NR; r++) st[r] = xbuf[ADDR_D(t, r)];
    __syncthreads();
}
__device__ __forceinline__ void exch_D_to_C(u64* st, int t, u64* xbuf) {
#pragma unroll
    for (int r = 0; r < NR; r++) xbuf[ADDR_D(t, r)] = st[r];
    __syncthreads();
#pragma unroll
    for (int r = 0; r < NR; r++) st[r] = xbuf[ADDR_C(t, r)];
    __syncwarp();   // readers touched warp-local rows only; next writer is same-warp
}

// ======================= sweeps =======================
__device__ __forceinline__ void sweep_A_to_D(u64* st, const u64* G, int t, u64* x) {
    gate_reg<3>(st, G +  8 * 8);  gate_reg<2>(st, G +  9 * 8);
    gate_reg<1>(st, G + 10 * 8);  gate_reg<0>(st, G + 11 * 8);
    exch_A_to_C(st, t, x);
    gate_reg<3>(st, G +  4 * 8);  gate_reg<2>(st, G +  5 * 8);
    gate_reg<1>(st, G +  6 * 8);  gate_reg<0>(st, G +  7 * 8);
    exch_C_to_D(st, t, x);
    gate_reg<3>(st, G +  0 * 8);  gate_reg<2>(st, G +  1 * 8);
    gate_reg<1>(st, G +  2 * 8);  gate_reg<0>(st, G +  3 * 8);
}
__device__ __forceinline__ void sweep_D_to_A(u64* st, const u64* G, int t, u64* x) {
    gate_reg<3>(st, G +  0 * 8);  gate_reg<2>(st, G +  1 * 8);
    gate_reg<1>(st, G +  2 * 8);  gate_reg<0>(st, G +  3 * 8);
    exch_D_to_C(st, t, x);
    gate_reg<3>(st, G +  4 * 8);  gate_reg<2>(st, G +  5 * 8);
    gate_reg<1>(st, G +  6 * 8);  gate_reg<0>(st, G +  7 * 8);
    exch_C_to_A(st, t, x);
    gate_reg<3>(st, G +  8 * 8);  gate_reg<2>(st, G +  9 * 8);
    gate_reg<1>(st, G + 10 * 8);  gate_reg<0>(st, G + 11 * 8);
}

// ======================= batched CNOT ring: ONE smem round-trip =======================
// Circuit: for k=0..11, if mask_k: CNOT(ctrl wire k, tgt wire (k+1)%12).
// Amplitude map: psi'(n) = psi(T0(T1(...T11(n)))) — apply T_k in REVERSE order to dst index.
// T_k(n) = n ^ (((n>>cb)&1)<<tb), cb = 11-k, tb = 11-((k+1)%12). All masks CTA-uniform.
template<bool LAYOUT_A>
__device__ __forceinline__ void cnotx(u64* st, int t, u64* x, unsigned mask) {
#pragma unroll
    for (int r = 0; r < NR; r++) {
        unsigned n = LAYOUT_A ? (((unsigned)t << 4) | (unsigned)r)
                              : (((unsigned)r << 8) | (unsigned)t);
        x[n + (n >> 4)] = st[r];
    }
    __syncthreads();
    unsigned m[NR];
#pragma unroll
    for (int r = 0; r < NR; r++)
        m[r] = LAYOUT_A ? (((unsigned)t << 4) | (unsigned)r)
                        : (((unsigned)r << 8) | (unsigned)t);
#pragma unroll
    for (int k = NQ - 1; k >= 0; k--) {
        if (mask & (1u << k)) {               // uniform branch
            const int cb = 11 - k;
            const int tb = 11 - ((k + 1) % NQ);
#pragma unroll
            for (int r = 0; r < NR; r++)
                m[r] ^= ((m[r] >> cb) & 1u) << tb;
        }
    }
#pragma unroll
    for (int r = 0; r < NR; r++) st[r] = x[m[r] + (m[r] >> 4)];
    __syncthreads();
}

__global__ void __launch_bounds__(NT)
qsim_kernel(const float* __restrict__ x,       // (B, 12)
            const float* __restrict__ w,       // (4, 12, 3)
            const float* __restrict__ ent,     // (4, 12)
            float* __restrict__ out)           // (B, 12)
{
    __shared__ __align__(16) u64 Usm[NGATES * 8];   // 3840 B gate coefficients
    __shared__ u64   xbuf[NT * XP];                 // 34816 B padded exchange buffer
    __shared__ float red[(NT / 32) * NQ];
    __shared__ unsigned char mflag[NLAYERS * NQ];
    __shared__ unsigned maskbits[NLAYERS];

    const int b    = blockIdx.x;
    const int t    = threadIdx.x;
    const int lane = t & 31;

    // ---- precompute all 60 gate matrices (one thread per gate) ----
    if (t < NGATES) {
        const float PI = 3.14159265358979323846f;
        float2 u00, u01, u10, u11;
        if (t < NQ) {
            float xv = __ldg(&x[b * NQ + t]);
            float s, c;  sincosf(0.5f * PI * xv, &s, &c);
            float sh, ch; sincosf(0.5f * PI * xv * xv, &sh, &ch);
            u00 = make_float2( c * ch, -c * sh);
            u01 = make_float2(-s * ch,  s * sh);
            u10 = make_float2( s * ch,  s * sh);
            u11 = make_float2( c * ch,  c * sh);
        } else {
            int gi = t - NQ;   // = l*12 + q
            float phi = __ldg(&w[gi * 3 + 0]);
            float th  = __ldg(&w[gi * 3 + 1]);
            float om  = __ldg(&w[gi * 3 + 2]);
            float s, c;  sincosf(0.5f * th, &s, &c);
            float sp, cp; sincosf(0.5f * (om + phi), &sp, &cp);
            float sm, cm; sincosf(0.5f * (om - phi), &sm, &cm);
            u00 = make_float2( c * cp, -c * sp);
            u01 = make_float2(-s * cm,  s * sm);
            u10 = make_float2( s * cm,  s * sm);
            u11 = make_float2( c * cp,  c * sp);
        }
        u64* g = &Usm[t * 8];
        g[0] = pack2(u00.x, u00.x);  g[1] = pack2(-u00.y, u00.y);
        g[2] = pack2(u01.x, u01.x);  g[3] = pack2(-u01.y, u01.y);
        g[4] = pack2(u10.x, u10.x);  g[5] = pack2(-u10.y, u10.y);
        g[6] = pack2(u11.x, u11.x);  g[7] = pack2(-u11.y, u11.y);
    }
    if (t < NLAYERS * NQ) mflag[t] = (__ldg(&ent[t]) > 0.5f) ? 1 : 0;
    __syncthreads();
    if (t < NLAYERS) {
        unsigned mm = 0;
#pragma unroll
        for (int i = 0; i < NQ; i++) mm |= (unsigned)mflag[t * NQ + i] << i;
        maskbits[t] = mm;
    }
    // maskbits published by the syncthreads inside the encoding sweep (exch_C_to_D),
    // before first use at layer 0.

    // ---- register-resident state, layout A: amp (t<<4)|r in st[r] ----
    u64 st[NR];
#pragma unroll
    for (int r = 0; r < NR; r++) st[r] = 0ULL;
    if (t == 0) st[0] = pack2(1.0f, 0.0f);

    // encoding sweep: A -> D
    sweep_A_to_D(st, Usm, t, xbuf);

    // variational layers: sweeps alternate D->A / A->D; CNOT rings batched into
    // one permutation round-trip each; layer 3's ring folded into readout signs.
    {
        const u64* G0 = &Usm[(NQ + 0 * NQ) * 8];
        sweep_D_to_A(st, G0, t, xbuf);
        unsigned mk = maskbits[0];
        if (mk) cnotx<true>(st, t, xbuf, mk);

        const u64* G1 = &Usm[(NQ + 1 * NQ) * 8];
        sweep_A_to_D(st, G1, t, xbuf);
        mk = maskbits[1];
        if (mk) cnotx<false>(st, t, xbuf, mk);

        const u64* G2 = &Usm[(NQ + 2 * NQ) * 8];
        sweep_D_to_A(st, G2, t, xbuf);
        mk = maskbits[2];
        if (mk) cnotx<true>(st, t, xbuf, mk);

        const u64* G3 = &Usm[(NQ + 3 * NQ) * 8];
        sweep_A_to_D(st, G3, t, xbuf);
        // layer 3 CNOT ring folded into readout below (pure basis relabeling)
    }

    // ---- readout in layout D (n = (r<<8)|t), with layer-3 ring folded in ----
    // psi_final(s) = psi_now(src(s)) => <Z_q> = sum_n |psi_now(n)|^2 * sign_q(dst(n)),
    // dst(n) = T11(...T0(n)) applied in FORWARD ring order.
    unsigned v[NR];
#pragma unroll
    for (int r = 0; r < NR; r++) v[r] = ((unsigned)r << 8) | (unsigned)t;
    {
        unsigned mk3 = maskbits[3];
#pragma unroll
        for (int k = 0; k < NQ; k++) {
            if (mk3 & (1u << k)) {            // uniform branch
                const int cb = 11 - k;
                const int tb = 11 - ((k + 1) % NQ);
#pragma unroll
                for (int r = 0; r < NR; r++)
                    v[r] ^= ((v[r] >> cb) & 1u) << tb;
            }
        }
    }
    float acc[NQ];
#pragma unroll
    for (int q = 0; q < NQ; q++) acc[q] = 0.f;
#pragma unroll
    for (int r = 0; r < NR; r++) {
        float re, im; unpack2(st[r], re, im);
        float p = re * re + im * im;
#pragma unroll
        for (int q = 0; q < NQ; q++)
            acc[q] += ((v[r] >> (11 - q)) & 1u) ? -p : p;
    }

    const int wid = t >> 5;
#pragma unroll
    for (int q = 0; q < NQ; q++) {
        float vv = acc[q];
#pragma unroll
        for (int o = 16; o; o >>= 1) vv += __shfl_xor_sync(0xFFFFFFFFu, vv, o);
        if (lane == 0) red[wid * NQ + q] = vv;
    }
    __syncthreads();

    if (t < NQ) {
        float s = 0.f;
#pragma unroll
        for (int wi = 0; wi < NT / 32; wi++) s += red[wi * NQ + t];
        out[b * NQ + t] = s;   // SCALE = 1
    }
}

extern "C" void kernel_launch(void* const* d_in, const int* in_sizes, int n_in,
                              void* d_out, int out_size)
{
    const float* x   = (const float*)d_in[0];   // (B, 12)
    const float* w   = (const float*)d_in[1];   // (4, 12, 3)
    const float* ent = (const float*)d_in[2];   // (4, 12)
    float* out = (float*)d_out;                 // (B, 12)

    int B = in_sizes[0] / NQ;
    qsim_kernel<<<B, NT>>>(x, w, ent, out);
}

// round 7
// speedup vs baseline: 1.4303x; 1.1504x over previous
#include <cuda_runtime.h>

#define NQ      12
#define NT      256         // threads per CTA
#define NR      16          // amplitudes per thread
#define NLAYERS 4
#define NGATES  60          // 12 encoding + 48 Rot
#define XP      17          // padded row pitch (u64) -> conflict-free transposes

typedef unsigned long long u64;

// ---- packed f32x2 helpers (re in lo 32 bits, im in hi 32 bits) ----
__device__ __forceinline__ u64 pack2(float lo, float hi) {
    u64 r; asm("mov.b64 %0, {%1, %2};" : "=l"(r) : "f"(lo), "f"(hi)); return r;
}
__device__ __forceinline__ void unpack2(u64 v, float& lo, float& hi) {
    asm("mov.b64 {%0, %1}, %2;" : "=f"(lo), "=f"(hi) : "l"(v));
}
__device__ __forceinline__ u64 swap2(u64 v) {
    u64 r;
    asm("{\n\t.reg .b32 l, h;\n\tmov.b64 {l, h}, %1;\n\tmov.b64 %0, {h, l};\n\t}"
        : "=l"(r) : "l"(v));
    return r;
}
__device__ __forceinline__ u64 ffma2(u64 a, u64 b, u64 c) {
    u64 r; asm("fma.rn.f32x2 %0, %1, %2, %3;" : "=l"(r) : "l"(a), "l"(b), "l"(c)); return r;
}
__device__ __forceinline__ u64 fmul2(u64 a, u64 b) {
    u64 r; asm("mul.rn.f32x2 %0, %1, %2;" : "=l"(r) : "l"(a), "l"(b)); return r;
}
__device__ __forceinline__ float2 cmul(float2 a, float2 b) {
    return make_float2(fmaf(-a.y, b.y, a.x * b.x), fmaf(a.y, b.x, a.x * b.y));
}

// Gate coefficients per gate (8 u64): [A00 B00 A01 B01 A10 B10 A11 B11]
// A(c)=(re,re), B(c)=(-im,im): complex mul c*m = A*m + B*swap(m).

// ---- gate on register bit P: pure register FMA ----
template<int P>
__device__ __forceinline__ void gate_reg(u64* st, const u64* g) {
    ulonglong2 cA = *(const ulonglong2*)(g + 0);   // A00, B00
    ulonglong2 cB = *(const ulonglong2*)(g + 2);   // A01, B01
    ulonglong2 cC = *(const ulonglong2*)(g + 4);   // A10, B10
    ulonglong2 cD = *(const ulonglong2*)(g + 6);   // A11, B11
#pragma unroll
    for (int k = 0; k < NR / 2; k++) {
        const int r0 = ((k >> P) << (P + 1)) | (k & ((1 << P) - 1));
        const int r1 = r0 | (1 << P);
        u64 m0 = st[r0], m1 = st[r1];
        u64 s0 = swap2(m0), s1 = swap2(m1);
        st[r0] = ffma2(cB.x, m1, ffma2(cB.y, s1, ffma2(cA.y, s0, fmul2(cA.x, m0))));
        st[r1] = ffma2(cD.x, m1, ffma2(cD.y, s1, ffma2(cC.y, s0, fmul2(cC.x, m0))));
    }
}

// ======================= layouts & transposes =======================
// amp index n[11:0], wire q <-> bit (11-q). phys(n) = (n>>4)*XP + (n&15) = n + (n>>4).
// Layout A: n = (t<<4)|r                       wires 0..7 = t7..t0, 8..11 = r3..r0
// Layout C: n = ((t>>4)<<8)|(r<<4)|(t&15)      wires 0..3 = t7..t4, 4..7 = r3..r0, 8..11 = t3..t0
// Layout D: n = (r<<8)|t                       wires 0..3 = r3..r0, 4..11 = t7..t0

#define ADDR_A(t, r) ((t) * XP + (r))
#define ADDR_C(t, r) (((((t) >> 4) << 4) | (r)) * XP + ((t) & 15))
#define ADDR_D(t, r) ((((r) << 4) | ((t) >> 4)) * XP + ((t) & 15))

// A->C: warp-local (swaps lane bits with reg bits)
__device__ __forceinline__ void exch_A_to_C(u64* st, int t, u64* xbuf) {
#pragma unroll
    for (int r = 0; r < NR; r++) xbuf[ADDR_A(t, r)] = st[r];
    __syncwarp();
#pragma unroll
    for (int r = 0; r < NR; r++) st[r] = xbuf[ADDR_C(t, r)];
    __syncwarp();
}
__device__ __forceinline__ void exch_C_to_A(u64* st, int t, u64* xbuf) {
#pragma unroll
    for (int r = 0; r < NR; r++) xbuf[ADDR_C(t, r)] = st[r];
    __syncwarp();
#pragma unroll
    for (int r = 0; r < NR; r++) st[r] = xbuf[ADDR_A(t, r)];
    __syncwarp();
}
__device__ __forceinline__ void exch_C_to_D(u64* st, int t, u64* xbuf) {
#pragma unroll
    for (int r = 0; r < NR; r++) xbuf[ADDR_C(t, r)] = st[r];
    __syncthreads();
#pragma unroll
    for (int r = 0; r < NR; r++) st[r] = xbuf[ADDR_D(t, r)];
    __syncthreads();
}
__device__ __forceinline__ void exch_D_to_C(u64* st, int t, u64* xbuf) {
#pragma unroll
    for (int r = 0; r < NR; r++) xbuf[ADDR_D(t, r)] = st[r];
    __syncthreads();
#pragma unroll
    for (int r = 0; r < NR; r++) st[r] = xbuf[ADDR_C(t, r)];
    __syncwarp();   // readers touched warp-local rows only; next writer is same-warp
}

// ======================= sweeps =======================
__device__ __forceinline__ void sweep_A_to_D(u64* st, const u64* G, int t, u64* x) {
    gate_reg<3>(st, G +  8 * 8);  gate_reg<2>(st, G +  9 * 8);
    gate_reg<1>(st, G + 10 * 8);  gate_reg<0>(st, G + 11 * 8);
    exch_A_to_C(st, t, x);
    gate_reg<3>(st, G +  4 * 8);  gate_reg<2>(st, G +  5 * 8);
    gate_reg<1>(st, G +  6 * 8);  gate_reg<0>(st, G +  7 * 8);
    exch_C_to_D(st, t, x);
    gate_reg<3>(st, G +  0 * 8);  gate_reg<2>(st, G +  1 * 8);
    gate_reg<1>(st, G +  2 * 8);  gate_reg<0>(st, G +  3 * 8);
}
__device__ __forceinline__ void sweep_D_to_A(u64* st, const u64* G, int t, u64* x) {
    gate_reg<3>(st, G +  0 * 8);  gate_reg<2>(st, G +  1 * 8);
    gate_reg<1>(st, G +  2 * 8);  gate_reg<0>(st, G +  3 * 8);
    exch_D_to_C(st, t, x);
    gate_reg<3>(st, G +  4 * 8);  gate_reg<2>(st, G +  5 * 8);
    gate_reg<1>(st, G +  6 * 8);  gate_reg<0>(st, G +  7 * 8);
    exch_C_to_A(st, t, x);
    gate_reg<3>(st, G +  8 * 8);  gate_reg<2>(st, G +  9 * 8);
    gate_reg<1>(st, G + 10 * 8);  gate_reg<0>(st, G + 11 * 8);
}

// ======================= batched CNOT ring: ONE smem round-trip =======================
// Circuit: for k=0..11, if mask_k: CNOT(ctrl wire k, tgt wire (k+1)%12).
// Amplitude map: psi'(n) = psi(T0(T1(...T11(n)))) — apply T_k in REVERSE order to dst index.
// T_k(n) = n ^ (((n>>cb)&1)<<tb), cb = 11-k, tb = 11-((k+1)%12). All masks CTA-uniform.
template<bool LAYOUT_A>
__device__ __forceinline__ void cnotx(u64* st, int t, u64* x, unsigned mask) {
#pragma unroll
    for (int r = 0; r < NR; r++) {
        unsigned n = LAYOUT_A ? (((unsigned)t << 4) | (unsigned)r)
                              : (((unsigned)r << 8) | (unsigned)t);
        x[n + (n >> 4)] = st[r];
    }
    __syncthreads();
    unsigned m[NR];
#pragma unroll
    for (int r = 0; r < NR; r++)
        m[r] = LAYOUT_A ? (((unsigned)t << 4) | (unsigned)r)
                        : (((unsigned)r << 8) | (unsigned)t);
#pragma unroll
    for (int k = NQ - 1; k >= 0; k--) {
        if (mask & (1u << k)) {               // uniform branch
            const int cb = 11 - k;
            const int tb = 11 - ((k + 1) % NQ);
#pragma unroll
            for (int r = 0; r < NR; r++)
                m[r] ^= ((m[r] >> cb) & 1u) << tb;
        }
    }
#pragma unroll
    for (int r = 0; r < NR; r++) st[r] = x[m[r] + (m[r] >> 4)];
    __syncthreads();
}

__global__ void __launch_bounds__(NT)
qsim_kernel(const float* __restrict__ x,       // (B, 12)
            const float* __restrict__ w,       // (4, 12, 3)
            const float* __restrict__ ent,     // (4, 12)
            float* __restrict__ out)           // (B, 12)
{
    __shared__ __align__(16) u64 Usm[NGATES * 8];   // gate coefficients
    __shared__ u64   xbuf[NT * XP];                 // 34816 B padded exchange buffer
    __shared__ float red[(NT / 32) * NQ];
    __shared__ float2 encV[NQ][2];                  // encoding column-0 amps: a_q(0), a_q(1)
    __shared__ unsigned char mflag[NLAYERS * NQ];
    __shared__ unsigned maskbits[NLAYERS];

    const int b    = blockIdx.x;
    const int t    = threadIdx.x;
    const int lane = t & 31;

    // ---- precompute gate matrices (one thread per gate) ----
    if (t < NGATES) {
        const float PI = 3.14159265358979323846f;
        float2 u00, u01, u10, u11;
        if (t < NQ) {
            // encoding on wire t: U = RZ(x^2*pi) @ RY(x*pi) — only column 0 needed
            float xv = __ldg(&x[b * NQ + t]);
            float s, c;  sincosf(0.5f * PI * xv, &s, &c);
            float sh, ch; sincosf(0.5f * PI * xv * xv, &sh, &ch);
            u00 = make_float2( c * ch, -c * sh);
            u10 = make_float2( s * ch,  s * sh);
            encV[t][0] = u00;
            encV[t][1] = u10;
        } else {
            int gi = t - NQ;   // = l*12 + q
            float phi = __ldg(&w[gi * 3 + 0]);
            float th  = __ldg(&w[gi * 3 + 1]);
            float om  = __ldg(&w[gi * 3 + 2]);
            float s, c;  sincosf(0.5f * th, &s, &c);
            float sp, cp; sincosf(0.5f * (om + phi), &sp, &cp);
            float sm, cm; sincosf(0.5f * (om - phi), &sm, &cm);
            u00 = make_float2( c * cp, -c * sp);
            u01 = make_float2(-s * cm,  s * sm);
            u10 = make_float2( s * cm,  s * sm);
            u11 = make_float2( c * cp,  c * sp);
            u64* g = &Usm[t * 8];
            g[0] = pack2(u00.x, u00.x);  g[1] = pack2(-u00.y, u00.y);
            g[2] = pack2(u01.x, u01.x);  g[3] = pack2(-u01.y, u01.y);
            g[4] = pack2(u10.x, u10.x);  g[5] = pack2(-u10.y, u10.y);
            g[6] = pack2(u11.x, u11.x);  g[7] = pack2(-u11.y, u11.y);
        }
    }
    if (t < NLAYERS * NQ) mflag[t] = (__ldg(&ent[t]) > 0.5f) ? 1 : 0;
    __syncthreads();
    if (t < NLAYERS) {
        unsigned mm = 0;
#pragma unroll
        for (int i = 0; i < NQ; i++) mm |= (unsigned)mflag[t * NQ + i] << i;
        maskbits[t] = mm;
    }
    // maskbits published by the first __syncthreads inside layer-0's sweep,
    // before first use in cnotx.

    // ---- encoded state is a PRODUCT state: psi(n) = prod_q a_q(bit_q(n)) ----
    // Build directly in layout D: n = (r<<8)|t; wires 0..3 = r3..r0, wires 4..11 = t7..t0.
    u64 st[NR];
    {
        float2 cm = encV[4][(t >> 7) & 1];
#pragma unroll
        for (int q = 5; q < NQ; q++)
            cm = cmul(cm, encV[q][(t >> (11 - q)) & 1]);
        float2 p01[4], p23[4];
#pragma unroll
        for (int i = 0; i < 4; i++) {
            p01[i] = cmul(encV[0][(i >> 1) & 1], encV[1][i & 1]);   // wires 0,1 (r3,r2)
            p23[i] = cmul(encV[2][(i >> 1) & 1], encV[3][i & 1]);   // wires 2,3 (r1,r0)
        }
#pragma unroll
        for (int r = 0; r < NR; r++) {
            float2 a = cmul(cmul(p01[r >> 2], p23[r & 3]), cm);
            st[r] = pack2(a.x, a.y);
        }
    }

    // variational layers: sweeps alternate D->A / A->D; CNOT rings batched into
    // one permutation round-trip each; layer 3's ring folded into readout signs.
    {
        const u64* G0 = &Usm[(NQ + 0 * NQ) * 8];
        sweep_D_to_A(st, G0, t, xbuf);
        unsigned mk = maskbits[0];
        if (mk) cnotx<true>(st, t, xbuf, mk);

        const u64* G1 = &Usm[(NQ + 1 * NQ) * 8];
        sweep_A_to_D(st, G1, t, xbuf);
        mk = maskbits[1];
        if (mk) cnotx<false>(st, t, xbuf, mk);

        const u64* G2 = &Usm[(NQ + 2 * NQ) * 8];
        sweep_D_to_A(st, G2, t, xbuf);
        mk = maskbits[2];
        if (mk) cnotx<true>(st, t, xbuf, mk);

        const u64* G3 = &Usm[(NQ + 3 * NQ) * 8];
        sweep_A_to_D(st, G3, t, xbuf);
        // layer 3 CNOT ring folded into readout below (pure basis relabeling)
    }

    // ---- readout in layout D (n = (r<<8)|t), with layer-3 ring folded in ----
    // psi_final(s) = psi_now(src(s)) => <Z_q> = sum_n |psi_now(n)|^2 * sign_q(dst(n)),
    // dst(n) = T11(...T0(n)) applied in FORWARD ring order.
    unsigned v[NR];
#pragma unroll
    for (int r = 0; r < NR; r++) v[r] = ((unsigned)r << 8) | (unsigned)t;
    {
        unsigned mk3 = maskbits[3];
#pragma unroll
        for (int k = 0; k < NQ; k++) {
            if (mk3 & (1u << k)) {            // uniform branch
                const int cb = 11 - k;
                const int tb = 11 - ((k + 1) % NQ);
#pragma unroll
                for (int r = 0; r < NR; r++)
                    v[r] ^= ((v[r] >> cb) & 1u) << tb;
            }
        }
    }
    float acc[NQ];
#pragma unroll
    for (int q = 0; q < NQ; q++) acc[q] = 0.f;
#pragma unroll
    for (int r = 0; r < NR; r++) {
        float re, im; unpack2(st[r], re, im);
        float p = re * re + im * im;
#pragma unroll
        for (int q = 0; q < NQ; q++)
            acc[q] += ((v[r] >> (11 - q)) & 1u) ? -p : p;
    }

    const int wid = t >> 5;
#pragma unroll
    for (int q = 0; q < NQ; q++) {
        float vv = acc[q];
#pragma unroll
        for (int o = 16; o; o >>= 1) vv += __shfl_xor_sync(0xFFFFFFFFu, vv, o);
        if (lane == 0) red[wid * NQ + q] = vv;
    }
    __syncthreads();

    if (t < NQ) {
        float s = 0.f;
#pragma unroll
        for (int wi = 0; wi < NT / 32; wi++) s += red[wi * NQ + t];
        out[b * NQ + t] = s;   // SCALE = 1
    }
}

extern "C" void kernel_launch(void* const* d_in, const int* in_sizes, int n_in,
                              void* d_out, int out_size)
{
    const float* x   = (const float*)d_in[0];   // (B, 12)
    const float* w   = (const float*)d_in[1];   // (4, 12, 3)
    const float* ent = (const float*)d_in[2];   // (4, 12)
    float* out = (float*)d_out;                 // (B, 12)

    int B = in_sizes[0] / NQ;
    qsim_kernel<<<B, NT>>>(x, w, ent, out);
}

// round 8
// speedup vs baseline: 1.5366x; 1.0743x over previous
#include <cuda_runtime.h>

#define NQ      12
#define NT      256         // threads per CTA
#define NR      16          // amplitudes per thread
#define NLAYERS 4
#define NGATES  60          // 12 encoding + 48 Rot
#define XP      17          // padded row pitch (u64) -> conflict-free transposes

typedef unsigned long long u64;

// ---- packed f32x2 helpers (re in lo 32 bits, im in hi 32 bits) ----
__device__ __forceinline__ u64 pack2(float lo, float hi) {
    u64 r; asm("mov.b64 %0, {%1, %2};" : "=l"(r) : "f"(lo), "f"(hi)); return r;
}
__device__ __forceinline__ void unpack2(u64 v, float& lo, float& hi) {
    asm("mov.b64 {%0, %1}, %2;" : "=f"(lo), "=f"(hi) : "l"(v));
}
__device__ __forceinline__ u64 swap2(u64 v) {
    u64 r;
    asm("{\n\t.reg .b32 l, h;\n\tmov.b64 {l, h}, %1;\n\tmov.b64 %0, {h, l};\n\t}"
        : "=l"(r) : "l"(v));
    return r;
}
__device__ __forceinline__ u64 ffma2(u64 a, u64 b, u64 c) {
    u64 r; asm("fma.rn.f32x2 %0, %1, %2, %3;" : "=l"(r) : "l"(a), "l"(b), "l"(c)); return r;
}
__device__ __forceinline__ u64 fmul2(u64 a, u64 b) {
    u64 r; asm("mul.rn.f32x2 %0, %1, %2;" : "=l"(r) : "l"(a), "l"(b)); return r;
}
__device__ __forceinline__ float2 cmul(float2 a, float2 b) {
    return make_float2(fmaf(-a.y, b.y, a.x * b.x), fmaf(a.y, b.x, a.x * b.y));
}

// Gate coefficients per gate (8 u64): [A00 B00 A01 B01 A10 B10 A11 B11]
// A(c)=(re,re), B(c)=(-im,im): complex mul c*m = A*m + B*swap(m).

// ---- gate on register bit P: pure register FMA ----
template<int P>
__device__ __forceinline__ void gate_reg(u64* st, const u64* g) {
    ulonglong2 cA = *(const ulonglong2*)(g + 0);   // A00, B00
    ulonglong2 cB = *(const ulonglong2*)(g + 2);   // A01, B01
    ulonglong2 cC = *(const ulonglong2*)(g + 4);   // A10, B10
    ulonglong2 cD = *(const ulonglong2*)(g + 6);   // A11, B11
#pragma unroll
    for (int k = 0; k < NR / 2; k++) {
        const int r0 = ((k >> P) << (P + 1)) | (k & ((1 << P) - 1));
        const int r1 = r0 | (1 << P);
        u64 m0 = st[r0], m1 = st[r1];
        u64 s0 = swap2(m0), s1 = swap2(m1);
        st[r0] = ffma2(cB.x, m1, ffma2(cB.y, s1, ffma2(cA.y, s0, fmul2(cA.x, m0))));
        st[r1] = ffma2(cD.x, m1, ffma2(cD.y, s1, ffma2(cC.y, s0, fmul2(cC.x, m0))));
    }
}

// ======================= layouts & transposes =======================
// amp index n[11:0], wire q <-> bit (11-q). phys(n) = (n>>4)*XP + (n&15) = n + (n>>4).
// Layout A: n = (t<<4)|r                       wires 0..7 = t7..t0, 8..11 = r3..r0
// Layout C: n = ((t>>4)<<8)|(r<<4)|(t&15)      wires 0..3 = t7..t4, 4..7 = r3..r0, 8..11 = t3..t0
// Layout D: n = (r<<8)|t                       wires 0..3 = r3..r0, 4..11 = t7..t0

#define ADDR_A(t, r) ((t) * XP + (r))
#define ADDR_C(t, r) (((((t) >> 4) << 4) | (r)) * XP + ((t) & 15))
#define ADDR_D(t, r) ((((r) << 4) | ((t) >> 4)) * XP + ((t) & 15))

// A->C: warp-local (swaps lane bits with reg bits)
__device__ __forceinline__ void exch_A_to_C(u64* st, int t, u64* xbuf) {
#pragma unroll
    for (int r = 0; r < NR; r++) xbuf[ADDR_A(t, r)] = st[r];
    __syncwarp();
#pragma unroll
    for (int r = 0; r < NR; r++) st[r] = xbuf[ADDR_C(t, r)];
    __syncwarp();
}
__device__ __forceinline__ void exch_C_to_A(u64* st, int t, u64* xbuf) {
#pragma unroll
    for (int r = 0; r < NR; r++) xbuf[ADDR_C(t, r)] = st[r];
    __syncwarp();
#pragma unroll
    for (int r = 0; r < NR; r++) st[r] = xbuf[ADDR_A(t, r)];
    __syncwarp();
}
__device__ __forceinline__ void exch_C_to_D(u64* st, int t, u64* xbuf) {
#pragma unroll
    for (int r = 0; r < NR; r++) xbuf[ADDR_C(t, r)] = st[r];
    __syncthreads();
#pragma unroll
    for (int r = 0; r < NR; r++) st[r] = xbuf[ADDR_D(t, r)];
    __syncthreads();
}
__device__ __forceinline__ void exch_D_to_C(u64* st, int t, u64* xbuf) {
#pragma unroll
    for (int r = 0; r < NR; r++) xbuf[ADDR_D(t, r)] = st[r];
    __syncthreads();
#pragma unroll
    for (int r = 0; r < NR; r++) st[r] = xbuf[ADDR_C(t, r)];
    __syncwarp();   // readers touched warp-local rows only; next writer is same-warp
}

// ======================= sweeps =======================
__device__ __forceinline__ void sweep_A_to_D(u64* st, const u64* G, int t, u64* x) {
    gate_reg<3>(st, G +  8 * 8);  gate_reg<2>(st, G +  9 * 8);
    gate_reg<1>(st, G + 10 * 8);  gate_reg<0>(st, G + 11 * 8);
    exch_A_to_C(st, t, x);
    gate_reg<3>(st, G +  4 * 8);  gate_reg<2>(st, G +  5 * 8);
    gate_reg<1>(st, G +  6 * 8);  gate_reg<0>(st, G +  7 * 8);
    exch_C_to_D(st, t, x);
    gate_reg<3>(st, G +  0 * 8);  gate_reg<2>(st, G +  1 * 8);
    gate_reg<1>(st, G +  2 * 8);  gate_reg<0>(st, G +  3 * 8);
}
__device__ __forceinline__ void sweep_D_to_A(u64* st, const u64* G, int t, u64* x) {
    gate_reg<3>(st, G +  0 * 8);  gate_reg<2>(st, G +  1 * 8);
    gate_reg<1>(st, G +  2 * 8);  gate_reg<0>(st, G +  3 * 8);
    exch_D_to_C(st, t, x);
    gate_reg<3>(st, G +  4 * 8);  gate_reg<2>(st, G +  5 * 8);
    gate_reg<1>(st, G +  6 * 8);  gate_reg<0>(st, G +  7 * 8);
    exch_C_to_A(st, t, x);
    gate_reg<3>(st, G +  8 * 8);  gate_reg<2>(st, G +  9 * 8);
    gate_reg<1>(st, G + 10 * 8);  gate_reg<0>(st, G + 11 * 8);
}

// ======================= batched CNOT ring (linearized): ONE round-trip =======================
// Circuit: for k=0..11, if mask_k: CNOT(ctrl wire k, tgt wire (k+1)%12).
// psi'(n) = psi(M(n)) where M = T0∘T1∘...∘T11 (reverse order), each T_k linear over GF(2):
// T_k(n) = n ^ (((n>>cb)&1)<<tb), cb=11-k, tb=11-((k+1)%12).
// Linearity: M(base ^ bits) = M(base) ^ M(bits). Evaluate M on 5 basis values only.
template<bool LAYOUT_A>
__device__ __forceinline__ void cnotx(u64* st, int t, u64* x, unsigned mask) {
#pragma unroll
    for (int r = 0; r < NR; r++) {
        unsigned n = LAYOUT_A ? (((unsigned)t << 4) | (unsigned)r)
                              : (((unsigned)r << 8) | (unsigned)t);
        x[n + (n >> 4)] = st[r];
    }
    __syncthreads();
    // basis: thread part + the 4 register-bit unit vectors
    unsigned v0 = LAYOUT_A ? ((unsigned)t << 4) : (unsigned)t;
    unsigned v1 = LAYOUT_A ? 8u : (1u << 11);   // r bit 3
    unsigned v2 = LAYOUT_A ? 4u : (1u << 10);   // r bit 2
    unsigned v3 = LAYOUT_A ? 2u : (1u <<  9);   // r bit 1
    unsigned v4 = LAYOUT_A ? 1u : (1u <<  8);   // r bit 0
#pragma unroll
    for (int k = NQ - 1; k >= 0; k--) {
        if (mask & (1u << k)) {               // CTA-uniform branch
            const int cb = 11 - k;
            const int tb = 11 - ((k + 1) % NQ);
            v0 ^= ((v0 >> cb) & 1u) << tb;
            v1 ^= ((v1 >> cb) & 1u) << tb;
            v2 ^= ((v2 >> cb) & 1u) << tb;
            v3 ^= ((v3 >> cb) & 1u) << tb;
            v4 ^= ((v4 >> cb) & 1u) << tb;
        }
    }
#pragma unroll
    for (int r = 0; r < NR; r++) {            // r compile-time -> constant-folded XOR tree
        unsigned m = v0;
        if (r & 8) m ^= v1;
        if (r & 4) m ^= v2;
        if (r & 2) m ^= v3;
        if (r & 1) m ^= v4;
        st[r] = x[m + (m >> 4)];
    }
    __syncthreads();
}

__device__ __forceinline__ float wred(float v) {
#pragma unroll
    for (int o = 16; o; o >>= 1) v += __shfl_xor_sync(0xFFFFFFFFu, v, o);
    return v;
}

__global__ void __launch_bounds__(NT)
qsim_kernel(const float* __restrict__ x,       // (B, 12)
            const float* __restrict__ w,       // (4, 12, 3)
            const float* __restrict__ ent,     // (4, 12)
            float* __restrict__ out)           // (B, 12)
{
    __shared__ __align__(16) u64 Usm[NGATES * 8];   // gate coefficients
    __shared__ u64   xbuf[NT * XP];                 // 34816 B padded exchange buffer
    __shared__ float red[(NT / 32) * NQ];
    __shared__ float2 encV[NQ][2];                  // encoding column-0 amps: a_q(0), a_q(1)
    __shared__ unsigned char mflag[NLAYERS * NQ];
    __shared__ unsigned maskbits[NLAYERS];

    const int b    = blockIdx.x;
    const int t    = threadIdx.x;
    const int lane = t & 31;
    const int wid  = t >> 5;

    // ---- precompute gate matrices (one thread per gate) ----
    if (t < NGATES) {
        const float PI = 3.14159265358979323846f;
        float2 u00, u01, u10, u11;
        if (t < NQ) {
            // encoding on wire t: U = RZ(x^2*pi) @ RY(x*pi) — only column 0 needed
            float xv = __ldg(&x[b * NQ + t]);
            float s, c;  sincosf(0.5f * PI * xv, &s, &c);
            float sh, ch; sincosf(0.5f * PI * xv * xv, &sh, &ch);
            encV[t][0] = make_float2( c * ch, -c * sh);
            encV[t][1] = make_float2( s * ch,  s * sh);
        } else {
            int gi = t - NQ;   // = l*12 + q
            float phi = __ldg(&w[gi * 3 + 0]);
            float th  = __ldg(&w[gi * 3 + 1]);
            float om  = __ldg(&w[gi * 3 + 2]);
            float s, c;  sincosf(0.5f * th, &s, &c);
            float sp, cp; sincosf(0.5f * (om + phi), &sp, &cp);
            float sm, cm; sincosf(0.5f * (om - phi), &sm, &cm);
            u00 = make_float2( c * cp, -c * sp);
            u01 = make_float2(-s * cm,  s * sm);
            u10 = make_float2( s * cm,  s * sm);
            u11 = make_float2( c * cp,  c * sp);
            u64* g = &Usm[t * 8];
            g[0] = pack2(u00.x, u00.x);  g[1] = pack2(-u00.y, u00.y);
            g[2] = pack2(u01.x, u01.x);  g[3] = pack2(-u01.y, u01.y);
            g[4] = pack2(u10.x, u10.x);  g[5] = pack2(-u10.y, u10.y);
            g[6] = pack2(u11.x, u11.x);  g[7] = pack2(-u11.y, u11.y);
        }
    }
    if (t < NLAYERS * NQ) mflag[t] = (__ldg(&ent[t]) > 0.5f) ? 1 : 0;
    __syncthreads();
    if (t < NLAYERS) {
        unsigned mm = 0;
#pragma unroll
        for (int i = 0; i < NQ; i++) mm |= (unsigned)mflag[t * NQ + i] << i;
        maskbits[t] = mm;
    }
    // maskbits published by the first __syncthreads inside layer-0's sweep,
    // before first use in cnotx.

    // ---- encoded state is a PRODUCT state: psi(n) = prod_q a_q(bit_q(n)) ----
    // Build directly in layout D: n = (r<<8)|t; wires 0..3 = r3..r0, wires 4..11 = t7..t0.
    u64 st[NR];
    {
        float2 cm = encV[4][(t >> 7) & 1];
#pragma unroll
        for (int q = 5; q < NQ; q++)
            cm = cmul(cm, encV[q][(t >> (11 - q)) & 1]);
        float2 p01[4], p23[4];
#pragma unroll
        for (int i = 0; i < 4; i++) {
            p01[i] = cmul(encV[0][(i >> 1) & 1], encV[1][i & 1]);   // wires 0,1 (r3,r2)
            p23[i] = cmul(encV[2][(i >> 1) & 1], encV[3][i & 1]);   // wires 2,3 (r1,r0)
        }
#pragma unroll
        for (int r = 0; r < NR; r++) {
            float2 a = cmul(cmul(p01[r >> 2], p23[r & 3]), cm);
            st[r] = pack2(a.x, a.y);
        }
    }

    // variational layers: sweeps alternate D->A / A->D; CNOT rings batched into
    // one linearized permutation round-trip each.
    {
        const u64* G0 = &Usm[(NQ + 0 * NQ) * 8];
        sweep_D_to_A(st, G0, t, xbuf);
        unsigned mk = maskbits[0];
        if (mk) cnotx<true>(st, t, xbuf, mk);

        const u64* G1 = &Usm[(NQ + 1 * NQ) * 8];
        sweep_A_to_D(st, G1, t, xbuf);
        mk = maskbits[1];
        if (mk) cnotx<false>(st, t, xbuf, mk);

        const u64* G2 = &Usm[(NQ + 2 * NQ) * 8];
        sweep_D_to_A(st, G2, t, xbuf);
        mk = maskbits[2];
        if (mk) cnotx<true>(st, t, xbuf, mk);

        const u64* G3 = &Usm[(NQ + 3 * NQ) * 8];
        sweep_A_to_D(st, G3, t, xbuf);
        mk = maskbits[3];
        if (mk) cnotx<false>(st, t, xbuf, mk);   // explicit final ring (layout D)
    }

    // ---- readout in layout D: wires 0..3 = r3..r0, wires 4..6 = t7..t5 (warp bits),
    //      wires 7..11 = t4..t0 (lane bits) ----
    float psum = 0.f, a0 = 0.f, a1 = 0.f, a2 = 0.f, a3 = 0.f;
#pragma unroll
    for (int r = 0; r < NR; r++) {
        float re, im; unpack2(st[r], re, im);
        float p = fmaf(re, re, im * im);
        psum += p;
        a0 += (r & 8) ? -p : p;   // wire 0 = r3
        a1 += (r & 4) ? -p : p;   // wire 1 = r2
        a2 += (r & 2) ? -p : p;   // wire 2 = r1
        a3 += (r & 1) ? -p : p;   // wire 3 = r0
    }
    float ra0 = wred(a0), ra1 = wred(a1), ra2 = wred(a2), ra3 = wred(a3);
    float ps  = wred(psum);
    float s7  = wred((lane & 16) ? -psum : psum);   // wire 7  = t4
    float s8  = wred((lane &  8) ? -psum : psum);   // wire 8  = t3
    float s9  = wred((lane &  4) ? -psum : psum);   // wire 9  = t2
    float s10 = wred((lane &  2) ? -psum : psum);   // wire 10 = t1
    float s11 = wred((lane &  1) ? -psum : psum);   // wire 11 = t0
    if (lane == 0) {
        float* rw = &red[wid * NQ];
        rw[0] = ra0;  rw[1] = ra1;  rw[2] = ra2;  rw[3] = ra3;
        rw[4] = (wid & 4) ? -ps : ps;    // wire 4 = t7
        rw[5] = (wid & 2) ? -ps : ps;    // wire 5 = t6
        rw[6] = (wid & 1) ? -ps : ps;    // wire 6 = t5
        rw[7] = s7;  rw[8] = s8;  rw[9] = s9;  rw[10] = s10;  rw[11] = s11;
    }
    __syncthreads();

    if (t < NQ) {
        float s = 0.f;
#pragma unroll
        for (int wi = 0; wi < NT / 32; wi++) s += red[wi * NQ + t];
        out[b * NQ + t] = s;   // SCALE = 1
    }
}

extern "C" void kernel_launch(void* const* d_in, const int* in_sizes, int n_in,
                              void* d_out, int out_size)
{
    const float* x   = (const float*)d_in[0];   // (B, 12)
    const float* w   = (const float*)d_in[1];   // (4, 12, 3)
    const float* ent = (const float*)d_in[2];   // (4, 12)
    float* out = (float*)d_out;                 // (B, 12)

    int B = in_sizes[0] / NQ;
    qsim_kernel<<<B, NT>>>(x, w, ent, out);
}

// round 9
// speedup vs baseline: 1.8097x; 1.1778x over previous
#include <cuda_runtime.h>

#define NQ      12
#define NT      256         // threads per CTA
#define NR      16          // amplitudes per thread
#define NLAYERS 4
#define XP      17          // padded row pitch (u64) -> conflict-free transposes

typedef unsigned long long u64;

// ---- packed f32x2 helpers (re in lo 32 bits, im in hi 32 bits) ----
__device__ __forceinline__ u64 pack2(float lo, float hi) {
    u64 r; asm("mov.b64 %0, {%1, %2};" : "=l"(r) : "f"(lo), "f"(hi)); return r;
}
__device__ __forceinline__ void unpack2(u64 v, float& lo, float& hi) {
    asm("mov.b64 {%0, %1}, %2;" : "=f"(lo), "=f"(hi) : "l"(v));
}
__device__ __forceinline__ u64 swap2(u64 v) {
    u64 r;
    asm("{\n\t.reg .b32 l, h;\n\tmov.b64 {l, h}, %1;\n\tmov.b64 %0, {h, l};\n\t}"
        : "=l"(r) : "l"(v));
    return r;
}
__device__ __forceinline__ u64 ffma2(u64 a, u64 b, u64 c) {
    u64 r; asm("fma.rn.f32x2 %0, %1, %2, %3;" : "=l"(r) : "l"(a), "l"(b), "l"(c)); return r;
}
__device__ __forceinline__ u64 fmul2(u64 a, u64 b) {
    u64 r; asm("mul.rn.f32x2 %0, %1, %2;" : "=l"(r) : "l"(a), "l"(b)); return r;
}
__device__ __forceinline__ float2 cmul(float2 a, float2 b) {
    return make_float2(fmaf(-a.y, b.y, a.x * b.x), fmaf(a.y, b.x, a.x * b.y));
}

// ---- REAL RY gate on register bit P: 4 packed FMAs per pair, no swaps ----
// coeffs per gate (4 u64, stride 4): [C=(c,c), S=(s,s), NS=(-s,-s), pad]
template<int P>
__device__ __forceinline__ void gate_ry(u64* st, const u64* g) {
    ulonglong2 cs = *(const ulonglong2*)(g);   // C, S
    u64 NS = g[2];
#pragma unroll
    for (int k = 0; k < NR / 2; k++) {
        const int r0 = ((k >> P) << (P + 1)) | (k & ((1 << P) - 1));
        const int r1 = r0 | (1 << P);
        u64 m0 = st[r0], m1 = st[r1];
        st[r0] = ffma2(NS,   m1, fmul2(cs.x, m0));   // c*m0 - s*m1
        st[r1] = ffma2(cs.x, m1, fmul2(cs.y, m0));   // s*m0 + c*m1
    }
}

// ======================= layouts & transposes =======================
// amp index n[11:0], wire q <-> bit (11-q). phys(n) = n + (n>>4).
// Layout A: n = (t<<4)|r     wires 0..7 = t7..t0, 8..11 = r3..r0
// Layout C: n = ((t>>4)<<8)|(r<<4)|(t&15)
// Layout D: n = (r<<8)|t     wires 0..3 = r3..r0, 4..11 = t7..t0

#define ADDR_A(t, r) ((t) * XP + (r))
#define ADDR_C(t, r) (((((t) >> 4) << 4) | (r)) * XP + ((t) & 15))
#define ADDR_D(t, r) ((((r) << 4) | ((t) >> 4)) * XP + ((t) & 15))

__device__ __forceinline__ void exch_A_to_C(u64* st, int t, u64* xbuf) {
#pragma unroll
    for (int r = 0; r < NR; r++) xbuf[ADDR_A(t, r)] = st[r];
    __syncwarp();
#pragma unroll
    for (int r = 0; r < NR; r++) st[r] = xbuf[ADDR_C(t, r)];
    __syncwarp();
}
__device__ __forceinline__ void exch_C_to_A(u64* st, int t, u64* xbuf) {
#pragma unroll
    for (int r = 0; r < NR; r++) xbuf[ADDR_C(t, r)] = st[r];
    __syncwarp();
#pragma unroll
    for (int r = 0; r < NR; r++) st[r] = xbuf[ADDR_A(t, r)];
    __syncwarp();
}
__device__ __forceinline__ void exch_C_to_D(u64* st, int t, u64* xbuf) {
#pragma unroll
    for (int r = 0; r < NR; r++) xbuf[ADDR_C(t, r)] = st[r];
    __syncthreads();
#pragma unroll
    for (int r = 0; r < NR; r++) st[r] = xbuf[ADDR_D(t, r)];
    __syncthreads();
}
__device__ __forceinline__ void exch_D_to_C(u64* st, int t, u64* xbuf) {
#pragma unroll
    for (int r = 0; r < NR; r++) xbuf[ADDR_D(t, r)] = st[r];
    __syncthreads();
#pragma unroll
    for (int r = 0; r < NR; r++) st[r] = xbuf[ADDR_C(t, r)];
    __syncwarp();
}

// ======================= RY-only sweeps (phases pulled out) =======================
// gate coeffs for wire q at G + q*4
__device__ __forceinline__ void sweep_A_to_D(u64* st, const u64* G, int t, u64* x) {
    gate_ry<3>(st, G +  8 * 4);  gate_ry<2>(st, G +  9 * 4);
    gate_ry<1>(st, G + 10 * 4);  gate_ry<0>(st, G + 11 * 4);
    exch_A_to_C(st, t, x);
    gate_ry<3>(st, G +  4 * 4);  gate_ry<2>(st, G +  5 * 4);
    gate_ry<1>(st, G +  6 * 4);  gate_ry<0>(st, G +  7 * 4);
    exch_C_to_D(st, t, x);
    gate_ry<3>(st, G +  0 * 4);  gate_ry<2>(st, G +  1 * 4);
    gate_ry<1>(st, G +  2 * 4);  gate_ry<0>(st, G +  3 * 4);
}
__device__ __forceinline__ void sweep_D_to_A(u64* st, const u64* G, int t, u64* x) {
    gate_ry<3>(st, G +  0 * 4);  gate_ry<2>(st, G +  1 * 4);
    gate_ry<1>(st, G +  2 * 4);  gate_ry<0>(st, G +  3 * 4);
    exch_D_to_C(st, t, x);
    gate_ry<3>(st, G +  4 * 4);  gate_ry<2>(st, G +  5 * 4);
    gate_ry<1>(st, G +  6 * 4);  gate_ry<0>(st, G +  7 * 4);
    exch_C_to_A(st, t, x);
    gate_ry<3>(st, G +  8 * 4);  gate_ry<2>(st, G +  9 * 4);
    gate_ry<1>(st, G + 10 * 4);  gate_ry<0>(st, G + 11 * 4);
}

// ======================= global diagonal application =======================
// P[q][b] = per-wire unit phase for wire q, bit b. Diagonal = tensor product.
// Layout A: wires 0..7 <-> t7..t0 (thread), wires 8..11 <-> r3..r0 (register).
__device__ __forceinline__ void diag_A(u64* st, int t, const float2 (*P)[2]) {
    float2 ph = P[0][(t >> 7) & 1];
#pragma unroll
    for (int q = 1; q < 8; q++) ph = cmul(ph, P[q][(t >> (7 - q)) & 1]);
    u64 Ah[4], Bh[4], Al[4], Bl[4];
#pragma unroll
    for (int i = 0; i < 4; i++) {
        float2 hi = cmul(ph, cmul(P[8][(i >> 1) & 1], P[9][i & 1]));
        float2 lo = cmul(P[10][(i >> 1) & 1], P[11][i & 1]);
        Ah[i] = pack2(hi.x, hi.x);  Bh[i] = pack2(-hi.y, hi.y);
        Al[i] = pack2(lo.x, lo.x);  Bl[i] = pack2(-lo.y, lo.y);
    }
#pragma unroll
    for (int r = 0; r < NR; r++) {
        u64 a = st[r];
        a = ffma2(Bh[r >> 2], swap2(a), fmul2(Ah[r >> 2], a));
        a = ffma2(Bl[r & 3],  swap2(a), fmul2(Al[r & 3],  a));
        st[r] = a;
    }
}
// Layout D: wires 4..11 <-> t7..t0 (thread), wires 0..3 <-> r3..r0 (register).
__device__ __forceinline__ void diag_D(u64* st, int t, const float2 (*P)[2]) {
    float2 ph = P[4][(t >> 7) & 1];
#pragma unroll
    for (int q = 5; q < 12; q++) ph = cmul(ph, P[q][(t >> (11 - q)) & 1]);
    u64 Ah[4], Bh[4], Al[4], Bl[4];
#pragma unroll
    for (int i = 0; i < 4; i++) {
        float2 hi = cmul(ph, cmul(P[0][(i >> 1) & 1], P[1][i & 1]));
        float2 lo = cmul(P[2][(i >> 1) & 1], P[3][i & 1]);
        Ah[i] = pack2(hi.x, hi.x);  Bh[i] = pack2(-hi.y, hi.y);
        Al[i] = pack2(lo.x, lo.x);  Bl[i] = pack2(-lo.y, lo.y);
    }
#pragma unroll
    for (int r = 0; r < NR; r++) {
        u64 a = st[r];
        a = ffma2(Bh[r >> 2], swap2(a), fmul2(Ah[r >> 2], a));
        a = ffma2(Bl[r & 3],  swap2(a), fmul2(Al[r & 3],  a));
        st[r] = a;
    }
}

// ======================= batched CNOT ring (linearized GF(2)) =======================
template<bool LAYOUT_A>
__device__ __forceinline__ void cnotx(u64* st, int t, u64* x, unsigned mask) {
#pragma unroll
    for (int r = 0; r < NR; r++) {
        unsigned n = LAYOUT_A ? (((unsigned)t << 4) | (unsigned)r)
                              : (((unsigned)r << 8) | (unsigned)t);
        x[n + (n >> 4)] = st[r];
    }
    __syncthreads();
    unsigned v0 = LAYOUT_A ? ((unsigned)t << 4) : (unsigned)t;
    unsigned v1 = LAYOUT_A ? 8u : (1u << 11);
    unsigned v2 = LAYOUT_A ? 4u : (1u << 10);
    unsigned v3 = LAYOUT_A ? 2u : (1u <<  9);
    unsigned v4 = LAYOUT_A ? 1u : (1u <<  8);
#pragma unroll
    for (int k = NQ - 1; k >= 0; k--) {
        if (mask & (1u << k)) {               // CTA-uniform branch
            const int cb = 11 - k;
            const int tb = 11 - ((k + 1) % NQ);
            v0 ^= ((v0 >> cb) & 1u) << tb;
            v1 ^= ((v1 >> cb) & 1u) << tb;
            v2 ^= ((v2 >> cb) & 1u) << tb;
            v3 ^= ((v3 >> cb) & 1u) << tb;
            v4 ^= ((v4 >> cb) & 1u) << tb;
        }
    }
#pragma unroll
    for (int r = 0; r < NR; r++) {
        unsigned m = v0;
        if (r & 8) m ^= v1;
        if (r & 4) m ^= v2;
        if (r & 2) m ^= v3;
        if (r & 1) m ^= v4;
        st[r] = x[m + (m >> 4)];
    }
    __syncthreads();
}

__device__ __forceinline__ float wred(float v) {
#pragma unroll
    for (int o = 16; o; o >>= 1) v += __shfl_xor_sync(0xFFFFFFFFu, v, o);
    return v;
}

__global__ void __launch_bounds__(NT)
qsim_kernel(const float* __restrict__ x,       // (B, 12)
            const float* __restrict__ w,       // (4, 12, 3)
            const float* __restrict__ ent,     // (4, 12)
            float* __restrict__ out)           // (B, 12)
{
    __shared__ __align__(16) u64 Usm[48 * 4];       // RY coeffs: C,S,NS,pad per gate
    __shared__ float2 Phs1[48][2];                  // RZ(phi) phases per gate per bit
    __shared__ float2 Phs2[48][2];                  // RZ(omega) phases per gate per bit
    __shared__ u64   xbuf[NT * XP];                 // 34816 B padded exchange buffer
    __shared__ float red[(NT / 32) * NQ];
    __shared__ float2 encV[NQ][2];                  // encoding amps with layer-0 D1 folded in
    __shared__ unsigned char mflag[NLAYERS * NQ];
    __shared__ unsigned maskbits[NLAYERS];

    const int b    = blockIdx.x;
    const int t    = threadIdx.x;
    const int lane = t & 31;
    const int wid  = t >> 5;

    // ---- precompute gates/phases (one thread per gate) ----
    if (t < 60) {
        const float PI = 3.14159265358979323846f;
        if (t < NQ) {
            // encoding on wire t: column 0 of RZ(x^2 pi) RY(x pi), times layer-0 RZ(phi)
            float xv = __ldg(&x[b * NQ + t]);
            float s, c;  sincosf(0.5f * PI * xv, &s, &c);
            float sh, ch; sincosf(0.5f * PI * xv * xv, &sh, &ch);
            float2 a0 = make_float2( c * ch, -c * sh);
            float2 a1 = make_float2( s * ch,  s * sh);
            float pf = __ldg(&w[t * 3 + 0]);        // layer 0, wire t: phi
            float sp, cp; sincosf(0.5f * pf, &sp, &cp);
            encV[t][0] = cmul(a0, make_float2(cp, -sp));
            encV[t][1] = cmul(a1, make_float2(cp,  sp));
        } else {
            int gi = t - NQ;   // = l*12 + q
            float phi = __ldg(&w[gi * 3 + 0]);
            float th  = __ldg(&w[gi * 3 + 1]);
            float om  = __ldg(&w[gi * 3 + 2]);
            float s, c;  sincosf(0.5f * th, &s, &c);
            u64* g = &Usm[gi * 4];
            g[0] = pack2(c, c);  g[1] = pack2(s, s);  g[2] = pack2(-s, -s);
            float sp, cp; sincosf(0.5f * phi, &sp, &cp);
            Phs1[gi][0] = make_float2(cp, -sp);
            Phs1[gi][1] = make_float2(cp,  sp);
            float so, co; sincosf(0.5f * om, &so, &co);
            Phs2[gi][0] = make_float2(co, -so);
            Phs2[gi][1] = make_float2(co,  so);
        }
    }
    if (t < NLAYERS * NQ) mflag[t] = (__ldg(&ent[t]) > 0.5f) ? 1 : 0;
    __syncthreads();
    if (t < NLAYERS) {
        unsigned mm = 0;
#pragma unroll
        for (int i = 0; i < NQ; i++) mm |= (unsigned)mflag[t * NQ + i] << i;
        maskbits[t] = mm;
    }
    // maskbits published by the first __syncthreads inside layer-0's sweep.

    // ---- encoded state (incl. layer-0 RZ(phi) diagonal) is a PRODUCT state ----
    // Build directly in layout D: n = (r<<8)|t; wires 0..3 = r3..r0, wires 4..11 = t7..t0.
    u64 st[NR];
    {
        float2 cm = encV[4][(t >> 7) & 1];
#pragma unroll
        for (int q = 5; q < NQ; q++)
            cm = cmul(cm, encV[q][(t >> (11 - q)) & 1]);
        float2 p01[4], p23[4];
#pragma unroll
        for (int i = 0; i < 4; i++) {
            p01[i] = cmul(encV[0][(i >> 1) & 1], encV[1][i & 1]);
            p23[i] = cmul(encV[2][(i >> 1) & 1], encV[3][i & 1]);
        }
#pragma unroll
        for (int r = 0; r < NR; r++) {
            float2 a = cmul(cmul(p01[r >> 2], p23[r & 3]), cm);
            st[r] = pack2(a.x, a.y);
        }
    }

    // ---- layers: RY sweep, D2 diag, CNOT perm, D1 diag of next layer ----
    {
        sweep_D_to_A(st, Usm +  0 * 48, t, xbuf);       // layer 0 RYs
        diag_A(st, t, &Phs2[0]);                        // D2_0
        unsigned mk = maskbits[0];
        if (mk) cnotx<true>(st, t, xbuf, mk);
        diag_A(st, t, &Phs1[12]);                       // D1_1

        sweep_A_to_D(st, Usm +  1 * 48, t, xbuf);       // layer 1 RYs
        diag_D(st, t, &Phs2[12]);                       // D2_1
        mk = maskbits[1];
        if (mk) cnotx<false>(st, t, xbuf, mk);
        diag_D(st, t, &Phs1[24]);                       // D1_2

        sweep_D_to_A(st, Usm +  2 * 48, t, xbuf);       // layer 2 RYs
        diag_A(st, t, &Phs2[24]);                       // D2_2
        mk = maskbits[2];
        if (mk) cnotx<true>(st, t, xbuf, mk);
        diag_A(st, t, &Phs1[36]);                       // D1_3

        sweep_A_to_D(st, Usm +  3 * 48, t, xbuf);       // layer 3 RYs
        // D2_3 dropped: |amp|^2 is phase-invariant (and perm preserves that)
        mk = maskbits[3];
        if (mk) cnotx<false>(st, t, xbuf, mk);
    }

    // ---- readout in layout D: wires 0..3 = r3..r0, 4..6 = warp bits, 7..11 = lane bits ----
    float psum = 0.f, a0 = 0.f, a1 = 0.f, a2 = 0.f, a3 = 0.f;
#pragma unroll
    for (int r = 0; r < NR; r++) {
        float re, im; unpack2(st[r], re, im);
        float p = fmaf(re, re, im * im);
        psum += p;
        a0 += (r & 8) ? -p : p;
        a1 += (r & 4) ? -p : p;
        a2 += (r & 2) ? -p : p;
        a3 += (r & 1) ? -p : p;
    }
    float ra0 = wred(a0), ra1 = wred(a1), ra2 = wred(a2), ra3 = wred(a3);
    float ps  = wred(psum);
    float s7  = wred((lane & 16) ? -psum : psum);
    float s8  = wred((lane &  8) ? -psum : psum);
    float s9  = wred((lane &  4) ? -psum : psum);
    float s10 = wred((lane &  2) ? -psum : psum);
    float s11 = wred((lane &  1) ? -psum : psum);
    if (lane == 0) {
        float* rw = &red[wid * NQ];
        rw[0] = ra0;  rw[1] = ra1;  rw[2] = ra2;  rw[3] = ra3;
        rw[4] = (wid & 4) ? -ps : ps;
        rw[5] = (wid & 2) ? -ps : ps;
        rw[6] = (wid & 1) ? -ps : ps;
        rw[7] = s7;  rw[8] = s8;  rw[9] = s9;  rw[10] = s10;  rw[11] = s11;
    }
    __syncthreads();

    if (t < NQ) {
        float s = 0.f;
#pragma unroll
        for (int wi = 0; wi < NT / 32; wi++) s += red[wi * NQ + t];
        out[b * NQ + t] = s;   // SCALE = 1
    }
}

extern "C" void kernel_launch(void* const* d_in, const int* in_sizes, int n_in,
                              void* d_out, int out_size)
{
    const float* x   = (const float*)d_in[0];   // (B, 12)
    const float* w   = (const float*)d_in[1];   // (4, 12, 3)
    const float* ent = (const float*)d_in[2];   // (4, 12)
    float* out = (float*)d_out;                 // (B, 12)

    int B = in_sizes[0] / NQ;
    qsim_kernel<<<B, NT>>>(x, w, ent, out);
}

// round 10
// speedup vs baseline: 1.8122x; 1.0014x over previous
#include <cuda_runtime.h>

#define NQ      12
#define NT      256         // threads per CTA
#define NR      16          // amplitudes per thread
#define NLAYERS 4
#define XP      17          // padded row pitch (u64) -> conflict-free transposes

typedef unsigned long long u64;

// ---- packed f32x2 helpers (re in lo 32 bits, im in hi 32 bits) ----
__device__ __forceinline__ u64 pack2(float lo, float hi) {
    u64 r; asm("mov.b64 %0, {%1, %2};" : "=l"(r) : "f"(lo), "f"(hi)); return r;
}
__device__ __forceinline__ void unpack2(u64 v, float& lo, float& hi) {
    asm("mov.b64 {%0, %1}, %2;" : "=f"(lo), "=f"(hi) : "l"(v));
}
__device__ __forceinline__ u64 swap2(u64 v) {
    u64 r;
    asm("{\n\t.reg .b32 l, h;\n\tmov.b64 {l, h}, %1;\n\tmov.b64 %0, {h, l};\n\t}"
        : "=l"(r) : "l"(v));
    return r;
}
__device__ __forceinline__ u64 ffma2(u64 a, u64 b, u64 c) {
    u64 r; asm("fma.rn.f32x2 %0, %1, %2, %3;" : "=l"(r) : "l"(a), "l"(b), "l"(c)); return r;
}
__device__ __forceinline__ u64 fmul2(u64 a, u64 b) {
    u64 r; asm("mul.rn.f32x2 %0, %1, %2;" : "=l"(r) : "l"(a), "l"(b)); return r;
}
__device__ __forceinline__ float2 cmul(float2 a, float2 b) {
    return make_float2(fmaf(-a.y, b.y, a.x * b.x), fmaf(a.y, b.x, a.x * b.y));
}

// ---- REAL RY gate on register bit P: 4 packed FMAs per pair, no swaps ----
// coeffs per gate (4 u64, stride 4): [C=(c,c), S=(s,s), NS=(-s,-s), pad]
template<int P>
__device__ __forceinline__ void gate_ry(u64* st, const u64* g) {
    ulonglong2 cs = *(const ulonglong2*)(g);   // C, S
    u64 NS = g[2];
#pragma unroll
    for (int k = 0; k < NR / 2; k++) {
        const int r0 = ((k >> P) << (P + 1)) | (k & ((1 << P) - 1));
        const int r1 = r0 | (1 << P);
        u64 m0 = st[r0], m1 = st[r1];
        st[r0] = ffma2(NS,   m1, fmul2(cs.x, m0));   // c*m0 - s*m1
        st[r1] = ffma2(cs.x, m1, fmul2(cs.y, m0));   // s*m0 + c*m1
    }
}

// ======================= layouts & transposes =======================
// amp index n[11:0], wire q <-> bit (11-q). phys(n) = n + (n>>4).
// Layout A: n = (t<<4)|r     wires 0..7 = t7..t0, 8..11 = r3..r0
// Layout C: n = ((t>>4)<<8)|(r<<4)|(t&15)
// Layout D: n = (r<<8)|t     wires 0..3 = r3..r0, 4..11 = t7..t0

#define ADDR_A(t, r) ((t) * XP + (r))
#define ADDR_C(t, r) (((((t) >> 4) << 4) | (r)) * XP + ((t) & 15))
#define ADDR_D(t, r) ((((r) << 4) | ((t) >> 4)) * XP + ((t) & 15))

__device__ __forceinline__ void exch_A_to_C(u64* st, int t, u64* xbuf) {
#pragma unroll
    for (int r = 0; r < NR; r++) xbuf[ADDR_A(t, r)] = st[r];
    __syncwarp();
#pragma unroll
    for (int r = 0; r < NR; r++) st[r] = xbuf[ADDR_C(t, r)];
    __syncwarp();
}
__device__ __forceinline__ void exch_C_to_A(u64* st, int t, u64* xbuf) {
#pragma unroll
    for (int r = 0; r < NR; r++) xbuf[ADDR_C(t, r)] = st[r];
    __syncwarp();
#pragma unroll
    for (int r = 0; r < NR; r++) st[r] = xbuf[ADDR_A(t, r)];
    __syncwarp();
}
__device__ __forceinline__ void exch_C_to_D(u64* st, int t, u64* xbuf) {
#pragma unroll
    for (int r = 0; r < NR; r++) xbuf[ADDR_C(t, r)] = st[r];
    __syncthreads();
#pragma unroll
    for (int r = 0; r < NR; r++) st[r] = xbuf[ADDR_D(t, r)];
    __syncthreads();
}
__device__ __forceinline__ void exch_D_to_C(u64* st, int t, u64* xbuf) {
#pragma unroll
    for (int r = 0; r < NR; r++) xbuf[ADDR_D(t, r)] = st[r];
    __syncthreads();
#pragma unroll
    for (int r = 0; r < NR; r++) st[r] = xbuf[ADDR_C(t, r)];
    __syncwarp();
}

// ======================= RY-only sweeps (phases pulled out) =======================
__device__ __forceinline__ void sweep_A_to_D(u64* st, const u64* G, int t, u64* x) {
    gate_ry<3>(st, G +  8 * 4);  gate_ry<2>(st, G +  9 * 4);
    gate_ry<1>(st, G + 10 * 4);  gate_ry<0>(st, G + 11 * 4);
    exch_A_to_C(st, t, x);
    gate_ry<3>(st, G +  4 * 4);  gate_ry<2>(st, G +  5 * 4);
    gate_ry<1>(st, G +  6 * 4);  gate_ry<0>(st, G +  7 * 4);
    exch_C_to_D(st, t, x);
    gate_ry<3>(st, G +  0 * 4);  gate_ry<2>(st, G +  1 * 4);
    gate_ry<1>(st, G +  2 * 4);  gate_ry<0>(st, G +  3 * 4);
}
__device__ __forceinline__ void sweep_D_to_A(u64* st, const u64* G, int t, u64* x) {
    gate_ry<3>(st, G +  0 * 4);  gate_ry<2>(st, G +  1 * 4);
    gate_ry<1>(st, G +  2 * 4);  gate_ry<0>(st, G +  3 * 4);
    exch_D_to_C(st, t, x);
    gate_ry<3>(st, G +  4 * 4);  gate_ry<2>(st, G +  5 * 4);
    gate_ry<1>(st, G +  6 * 4);  gate_ry<0>(st, G +  7 * 4);
    exch_C_to_A(st, t, x);
    gate_ry<3>(st, G +  8 * 4);  gate_ry<2>(st, G +  9 * 4);
    gate_ry<1>(st, G + 10 * 4);  gate_ry<0>(st, G + 11 * 4);
}

// ======================= global diagonal application =======================
__device__ __forceinline__ void diag_A(u64* st, int t, const float2 (*P)[2]) {
    float2 ph = P[0][(t >> 7) & 1];
#pragma unroll
    for (int q = 1; q < 8; q++) ph = cmul(ph, P[q][(t >> (7 - q)) & 1]);
    u64 Ah[4], Bh[4], Al[4], Bl[4];
#pragma unroll
    for (int i = 0; i < 4; i++) {
        float2 hi = cmul(ph, cmul(P[8][(i >> 1) & 1], P[9][i & 1]));
        float2 lo = cmul(P[10][(i >> 1) & 1], P[11][i & 1]);
        Ah[i] = pack2(hi.x, hi.x);  Bh[i] = pack2(-hi.y, hi.y);
        Al[i] = pack2(lo.x, lo.x);  Bl[i] = pack2(-lo.y, lo.y);
    }
#pragma unroll
    for (int r = 0; r < NR; r++) {
        u64 a = st[r];
        a = ffma2(Bh[r >> 2], swap2(a), fmul2(Ah[r >> 2], a));
        a = ffma2(Bl[r & 3],  swap2(a), fmul2(Al[r & 3],  a));
        st[r] = a;
    }
}
__device__ __forceinline__ void diag_D(u64* st, int t, const float2 (*P)[2]) {
    float2 ph = P[4][(t >> 7) & 1];
#pragma unroll
    for (int q = 5; q < 12; q++) ph = cmul(ph, P[q][(t >> (11 - q)) & 1]);
    u64 Ah[4], Bh[4], Al[4], Bl[4];
#pragma unroll
    for (int i = 0; i < 4; i++) {
        float2 hi = cmul(ph, cmul(P[0][(i >> 1) & 1], P[1][i & 1]));
        float2 lo = cmul(P[2][(i >> 1) & 1], P[3][i & 1]);
        Ah[i] = pack2(hi.x, hi.x);  Bh[i] = pack2(-hi.y, hi.y);
        Al[i] = pack2(lo.x, lo.x);  Bl[i] = pack2(-lo.y, lo.y);
    }
#pragma unroll
    for (int r = 0; r < NR; r++) {
        u64 a = st[r];
        a = ffma2(Bh[r >> 2], swap2(a), fmul2(Ah[r >> 2], a));
        a = ffma2(Bl[r & 3],  swap2(a), fmul2(Al[r & 3],  a));
        st[r] = a;
    }
}

// ======================= batched CNOT ring (precomputed GF(2) basis) =======================
// v0 = M(thread base) precomputed per layer; units = M(reg-bit unit vectors) in smem.
template<bool LAYOUT_A>
__device__ __forceinline__ void cnotx(u64* st, int t, u64* x, unsigned v0, const uint4* up) {
#pragma unroll
    for (int r = 0; r < NR; r++) {
        unsigned n = LAYOUT_A ? (((unsigned)t << 4) | (unsigned)r)
                              : (((unsigned)r << 8) | (unsigned)t);
        x[n + (n >> 4)] = st[r];
    }
    __syncthreads();
    uint4 u = *up;
#pragma unroll
    for (int r = 0; r < NR; r++) {            // r compile-time -> constant-folded XOR tree
        unsigned m = v0;
        if (r & 8) m ^= u.x;
        if (r & 4) m ^= u.y;
        if (r & 2) m ^= u.z;
        if (r & 1) m ^= u.w;
        st[r] = x[m + (m >> 4)];
    }
    __syncthreads();
}

// GF(2) ring transform (reverse order): M = T0∘T1∘...∘T11 restricted to active masks.
__device__ __forceinline__ unsigned ring_map(unsigned v, unsigned mask) {
#pragma unroll
    for (int k = NQ - 1; k >= 0; k--) {
        if (mask & (1u << k)) {               // CTA-uniform branch
            const int cb = 11 - k;
            const int tb = 11 - ((k + 1) % NQ);
            v ^= ((v >> cb) & 1u) << tb;
        }
    }
    return v;
}

__device__ __forceinline__ float wred(float v) {
#pragma unroll
    for (int o = 16; o; o >>= 1) v += __shfl_xor_sync(0xFFFFFFFFu, v, o);
    return v;
}

__global__ void __launch_bounds__(NT)
qsim_kernel(const float* __restrict__ x,       // (B, 12)
            const float* __restrict__ w,       // (4, 12, 3)
            const float* __restrict__ ent,     // (4, 12)
            float* __restrict__ out)           // (B, 12)
{
    __shared__ __align__(16) u64 Usm[48 * 4];       // RY coeffs: C,S,NS,pad per gate
    __shared__ float2 Phs1[48][2];                  // RZ(phi) phases per gate per bit
    __shared__ float2 Phs2[48][2];                  // RZ(omega) phases per gate per bit
    __shared__ u64   xbuf[NT * XP];                 // 34816 B padded exchange buffer
    __shared__ float red[(NT / 32) * NQ];
    __shared__ float2 encV[NQ][2];                  // encoding amps with layer-0 D1 folded in
    __shared__ unsigned maskbits[NLAYERS];
    __shared__ __align__(16) unsigned units_sm[NLAYERS][4];  // M(unit) images per layer

    const int b    = blockIdx.x;
    const int t    = threadIdx.x;
    const int lane = t & 31;
    const int wid  = t >> 5;

    // ---- precompute gates/phases/masks (parallel across threads) ----
    if (t < 64) {
        const float PI = 3.14159265358979323846f;
        if (t < NQ) {
            // encoding on wire t: column 0 of RZ(x^2 pi) RY(x pi), times layer-0 RZ(phi)
            float xv = __ldg(&x[b * NQ + t]);
            float s, c;  sincosf(0.5f * PI * xv, &s, &c);
            float sh, ch; sincosf(0.5f * PI * xv * xv, &sh, &ch);
            float2 a0 = make_float2( c * ch, -c * sh);
            float2 a1 = make_float2( s * ch,  s * sh);
            float pf = __ldg(&w[t * 3 + 0]);        // layer 0, wire t: phi
            float sp, cp; sincosf(0.5f * pf, &sp, &cp);
            encV[t][0] = cmul(a0, make_float2(cp, -sp));
            encV[t][1] = cmul(a1, make_float2(cp,  sp));
        } else if (t < 60) {
            int gi = t - NQ;   // = l*12 + q
            float phi = __ldg(&w[gi * 3 + 0]);
            float th  = __ldg(&w[gi * 3 + 1]);
            float om  = __ldg(&w[gi * 3 + 2]);
            float s, c;  sincosf(0.5f * th, &s, &c);
            u64* g = &Usm[gi * 4];
            g[0] = pack2(c, c);  g[1] = pack2(s, s);  g[2] = pack2(-s, -s);
            float sp, cp; sincosf(0.5f * phi, &sp, &cp);
            Phs1[gi][0] = make_float2(cp, -sp);
            Phs1[gi][1] = make_float2(cp,  sp);
            float so, co; sincosf(0.5f * om, &so, &co);
            Phs2[gi][0] = make_float2(co, -so);
            Phs2[gi][1] = make_float2(co,  so);
        } else {
            int l = t - 60;    // t in [60,64): build maskbits[l] directly
            unsigned mm = 0;
#pragma unroll
            for (int i = 0; i < NQ; i++)
                mm |= (__ldg(&ent[l * NQ + i]) > 0.5f ? 1u : 0u) << i;
            maskbits[l] = mm;
        }
    }
    __syncthreads();

    // ---- per-thread v0 (thread-base image under each layer's ring perm) ----
    // Layers alternate CNOT layout: l even -> A (base t<<4), l odd -> D (base t).
    unsigned v0s[NLAYERS];
#pragma unroll
    for (int l = 0; l < NLAYERS; l++)
        v0s[l] = ring_map((l & 1) ? (unsigned)t : ((unsigned)t << 4), maskbits[l]);

    // ---- unit images (threads 64..79; consumed after later CTA barriers) ----
    if (t >= 64 && t < 64 + NLAYERS * 4) {
        int l = (t - 64) >> 2, i = (t - 64) & 3;
        unsigned v = (l & 1) ? (1u << (11 - i)) : (8u >> i);
        units_sm[l][i] = ring_map(v, maskbits[l]);
    }

    // ---- encoded state (incl. layer-0 RZ(phi) diagonal) is a PRODUCT state ----
    // Build directly in layout D: n = (r<<8)|t; wires 0..3 = r3..r0, wires 4..11 = t7..t0.
    u64 st[NR];
    {
        float2 cm = encV[4][(t >> 7) & 1];
#pragma unroll
        for (int q = 5; q < NQ; q++)
            cm = cmul(cm, encV[q][(t >> (11 - q)) & 1]);
        float2 p01[4], p23[4];
#pragma unroll
        for (int i = 0; i < 4; i++) {
            p01[i] = cmul(encV[0][(i >> 1) & 1], encV[1][i & 1]);
            p23[i] = cmul(encV[2][(i >> 1) & 1], encV[3][i & 1]);
        }
#pragma unroll
        for (int r = 0; r < NR; r++) {
            float2 a = cmul(cmul(p01[r >> 2], p23[r & 3]), cm);
            st[r] = pack2(a.x, a.y);
        }
    }

    // ---- layers: RY sweep, D2 diag, CNOT perm, D1 diag of next layer ----
    {
        sweep_D_to_A(st, Usm +  0 * 48, t, xbuf);       // layer 0 RYs
        diag_A(st, t, &Phs2[0]);                        // D2_0
        if (maskbits[0]) cnotx<true>(st, t, xbuf, v0s[0],
                                     reinterpret_cast<const uint4*>(units_sm[0]));
        diag_A(st, t, &Phs1[12]);                       // D1_1

        sweep_A_to_D(st, Usm +  1 * 48, t, xbuf);       // layer 1 RYs
        diag_D(st, t, &Phs2[12]);                       // D2_1
        if (maskbits[1]) cnotx<false>(st, t, xbuf, v0s[1],
                                      reinterpret_cast<const uint4*>(units_sm[1]));
        diag_D(st, t, &Phs1[24]);                       // D1_2

        sweep_D_to_A(st, Usm +  2 * 48, t, xbuf);       // layer 2 RYs
        diag_A(st, t, &Phs2[24]);                       // D2_2
        if (maskbits[2]) cnotx<true>(st, t, xbuf, v0s[2],
                                     reinterpret_cast<const uint4*>(units_sm[2]));
        diag_A(st, t, &Phs1[36]);                       // D1_3

        sweep_A_to_D(st, Usm +  3 * 48, t, xbuf);       // layer 3 RYs
        // D2_3 dropped: |amp|^2 is phase-invariant
        if (maskbits[3]) cnotx<false>(st, t, xbuf, v0s[3],
                                      reinterpret_cast<const uint4*>(units_sm[3]));
    }

    // ---- readout in layout D: wires 0..3 = r3..r0, 4..6 = warp bits, 7..11 = lane bits ----
    float psum = 0.f, a0 = 0.f, a1 = 0.f, a2 = 0.f, a3 = 0.f;
#pragma unroll
    for (int r = 0; r < NR; r++) {
        float re, im; unpack2(st[r], re, im);
        float p = fmaf(re, re, im * im);
        psum += p;
        a0 += (r & 8) ? -p : p;
        a1 += (r & 4) ? -p : p;
        a2 += (r & 2) ? -p : p;
        a3 += (r & 1) ? -p : p;
    }
    float ra0 = wred(a0), ra1 = wred(a1), ra2 = wred(a2), ra3 = wred(a3);
    float ps  = wred(psum);
    float s7  = wred((lane & 16) ? -psum : psum);
    float s8  = wred((lane &  8) ? -psum : psum);
    float s9  = wred((lane &  4) ? -psum : psum);
    float s10 = wred((lane &  2) ? -psum : psum);
    float s11 = wred((lane &  1) ? -psum : psum);
    if (lane == 0) {
        float* rw = &red[wid * NQ];
        rw[0] = ra0;  rw[1] = ra1;  rw[2] = ra2;  rw[3] = ra3;
        rw[4] = (wid & 4) ? -ps : ps;
        rw[5] = (wid & 2) ? -ps : ps;
        rw[6] = (wid & 1) ? -ps : ps;
        rw[7] = s7;  rw[8] = s8;  rw[9] = s9;  rw[10] = s10;  rw[11] = s11;
    }
    __syncthreads();

    if (t < NQ) {
        float s = 0.f;
#pragma unroll
        for (int wi = 0; wi < NT / 32; wi++) s += red[wi * NQ + t];
        out[b * NQ + t] = s;   // SCALE = 1
    }
}

extern "C" void kernel_launch(void* const* d_in, const int* in_sizes, int n_in,
                              void* d_out, int out_size)
{
    const float* x   = (const float*)d_in[0];   // (B, 12)
    const float* w   = (const float*)d_in[1];   // (4, 12, 3)
    const float* ent = (const float*)d_in[2];   // (4, 12)
    float* out = (float*)d_out;                 // (B, 12)

    int B = in_sizes[0] / NQ;
    qsim_kernel<<<B, NT>>>(x, w, ent, out);
}

// round 11
// speedup vs baseline: 1.9594x; 1.0812x over previous
#include <cuda_runtime.h>

#define NQ      12
#define NT      256         // threads per CTA
#define NR      16          // amplitudes per thread
#define NLAYERS 4
#define XP      17          // padded row pitch (u64) -> conflict-free transposes
#define XSZ     (NT * XP)   // u64 elements per exchange buffer

typedef unsigned long long u64;

// ---- packed f32x2 helpers (re in lo 32 bits, im in hi 32 bits) ----
__device__ __forceinline__ u64 pack2(float lo, float hi) {
    u64 r; asm("mov.b64 %0, {%1, %2};" : "=l"(r) : "f"(lo), "f"(hi)); return r;
}
__device__ __forceinline__ void unpack2(u64 v, float& lo, float& hi) {
    asm("mov.b64 {%0, %1}, %2;" : "=f"(lo), "=f"(hi) : "l"(v));
}
__device__ __forceinline__ u64 swap2(u64 v) {
    u64 r;
    asm("{\n\t.reg .b32 l, h;\n\tmov.b64 {l, h}, %1;\n\tmov.b64 %0, {h, l};\n\t}"
        : "=l"(r) : "l"(v));
    return r;
}
__device__ __forceinline__ u64 ffma2(u64 a, u64 b, u64 c) {
    u64 r; asm("fma.rn.f32x2 %0, %1, %2, %3;" : "=l"(r) : "l"(a), "l"(b), "l"(c)); return r;
}
__device__ __forceinline__ u64 fmul2(u64 a, u64 b) {
    u64 r; asm("mul.rn.f32x2 %0, %1, %2;" : "=l"(r) : "l"(a), "l"(b)); return r;
}
__device__ __forceinline__ float2 cmul(float2 a, float2 b) {
    return make_float2(fmaf(-a.y, b.y, a.x * b.x), fmaf(a.y, b.x, a.x * b.y));
}

// ---- REAL RY gate on register bit P: 4 packed FMAs per pair, no swaps ----
// coeffs per gate (4 u64, stride 4): [C=(c,c), S=(s,s), NS=(-s,-s), pad]
template<int P>
__device__ __forceinline__ void gate_ry(u64* st, const u64* g) {
    ulonglong2 cs = *(const ulonglong2*)(g);   // C, S
    u64 NS = g[2];
#pragma unroll
    for (int k = 0; k < NR / 2; k++) {
        const int r0 = ((k >> P) << (P + 1)) | (k & ((1 << P) - 1));
        const int r1 = r0 | (1 << P);
        u64 m0 = st[r0], m1 = st[r1];
        st[r0] = ffma2(NS,   m1, fmul2(cs.x, m0));   // c*m0 - s*m1
        st[r1] = ffma2(cs.x, m1, fmul2(cs.y, m0));   // s*m0 + c*m1
    }
}

// ======================= layouts & transposes =======================
// amp index n[11:0], wire q <-> bit (11-q). phys(n) = n + (n>>4).
// Layout A: n = (t<<4)|r     wires 0..7 = t7..t0, 8..11 = r3..r0
// Layout C: n = ((t>>4)<<8)|(r<<4)|(t&15)
// Layout D: n = (r<<8)|t     wires 0..3 = r3..r0, 4..11 = t7..t0
// Double-buffer rule: CTA-wide round-trips alternate x0 (sweep exchanges) and
// x1 (cnot perms); one __syncthreads() per round-trip is then sufficient
// (reuse of a buffer is always fenced by the other buffer's barrier).
// Warp-local transposes (A<->C) touch only the warp's own 32-row slice of x0.

#define ADDR_A(t, r) ((t) * XP + (r))
#define ADDR_C(t, r) (((((t) >> 4) << 4) | (r)) * XP + ((t) & 15))
#define ADDR_D(t, r) ((((r) << 4) | ((t) >> 4)) * XP + ((t) & 15))

__device__ __forceinline__ void exch_A_to_C(u64* st, int t, u64* x) {   // warp-local
#pragma unroll
    for (int r = 0; r < NR; r++) x[ADDR_A(t, r)] = st[r];
    __syncwarp();
#pragma unroll
    for (int r = 0; r < NR; r++) st[r] = x[ADDR_C(t, r)];
    __syncwarp();
}
__device__ __forceinline__ void exch_C_to_A(u64* st, int t, u64* x) {   // warp-local
#pragma unroll
    for (int r = 0; r < NR; r++) x[ADDR_C(t, r)] = st[r];
    __syncwarp();
#pragma unroll
    for (int r = 0; r < NR; r++) st[r] = x[ADDR_A(t, r)];
    __syncwarp();
}
__device__ __forceinline__ void exch_C_to_D(u64* st, int t, u64* x) {   // CTA, 1 bar
#pragma unroll
    for (int r = 0; r < NR; r++) x[ADDR_C(t, r)] = st[r];
    __syncthreads();
#pragma unroll
    for (int r = 0; r < NR; r++) st[r] = x[ADDR_D(t, r)];
}
__device__ __forceinline__ void exch_D_to_C(u64* st, int t, u64* x) {   // CTA, 1 bar
#pragma unroll
    for (int r = 0; r < NR; r++) x[ADDR_D(t, r)] = st[r];
    __syncthreads();
#pragma unroll
    for (int r = 0; r < NR; r++) st[r] = x[ADDR_C(t, r)];
    __syncwarp();   // reads are own-slice; order before this warp's next WL write
}

// ======================= RY-only sweeps (phases pulled out) =======================
__device__ __forceinline__ void sweep_A_to_D(u64* st, const u64* G, int t, u64* x) {
    gate_ry<3>(st, G +  8 * 4);  gate_ry<2>(st, G +  9 * 4);
    gate_ry<1>(st, G + 10 * 4);  gate_ry<0>(st, G + 11 * 4);
    exch_A_to_C(st, t, x);
    gate_ry<3>(st, G +  4 * 4);  gate_ry<2>(st, G +  5 * 4);
    gate_ry<1>(st, G +  6 * 4);  gate_ry<0>(st, G +  7 * 4);
    exch_C_to_D(st, t, x);
    gate_ry<3>(st, G +  0 * 4);  gate_ry<2>(st, G +  1 * 4);
    gate_ry<1>(st, G +  2 * 4);  gate_ry<0>(st, G +  3 * 4);
}
__device__ __forceinline__ void sweep_D_to_A(u64* st, const u64* G, int t, u64* x) {
    gate_ry<3>(st, G +  0 * 4);  gate_ry<2>(st, G +  1 * 4);
    gate_ry<1>(st, G +  2 * 4);  gate_ry<0>(st, G +  3 * 4);
    exch_D_to_C(st, t, x);
    gate_ry<3>(st, G +  4 * 4);  gate_ry<2>(st, G +  5 * 4);
    gate_ry<1>(st, G +  6 * 4);  gate_ry<0>(st, G +  7 * 4);
    exch_C_to_A(st, t, x);
    gate_ry<3>(st, G +  8 * 4);  gate_ry<2>(st, G +  9 * 4);
    gate_ry<1>(st, G + 10 * 4);  gate_ry<0>(st, G + 11 * 4);
}

// ======================= global diagonal application =======================
__device__ __forceinline__ void diag_A(u64* st, int t, const float2 (*P)[2]) {
    float2 ph = P[0][(t >> 7) & 1];
#pragma unroll
    for (int q = 1; q < 8; q++) ph = cmul(ph, P[q][(t >> (7 - q)) & 1]);
    u64 Ah[4], Bh[4], Al[4], Bl[4];
#pragma unroll
    for (int i = 0; i < 4; i++) {
        float2 hi = cmul(ph, cmul(P[8][(i >> 1) & 1], P[9][i & 1]));
        float2 lo = cmul(P[10][(i >> 1) & 1], P[11][i & 1]);
        Ah[i] = pack2(hi.x, hi.x);  Bh[i] = pack2(-hi.y, hi.y);
        Al[i] = pack2(lo.x, lo.x);  Bl[i] = pack2(-lo.y, lo.y);
    }
#pragma unroll
    for (int r = 0; r < NR; r++) {
        u64 a = st[r];
        a = ffma2(Bh[r >> 2], swap2(a), fmul2(Ah[r >> 2], a));
        a = ffma2(Bl[r & 3],  swap2(a), fmul2(Al[r & 3],  a));
        st[r] = a;
    }
}
__device__ __forceinline__ void diag_D(u64* st, int t, const float2 (*P)[2]) {
    float2 ph = P[4][(t >> 7) & 1];
#pragma unroll
    for (int q = 5; q < 12; q++) ph = cmul(ph, P[q][(t >> (11 - q)) & 1]);
    u64 Ah[4], Bh[4], Al[4], Bl[4];
#pragma unroll
    for (int i = 0; i < 4; i++) {
        float2 hi = cmul(ph, cmul(P[0][(i >> 1) & 1], P[1][i & 1]));
        float2 lo = cmul(P[2][(i >> 1) & 1], P[3][i & 1]);
        Ah[i] = pack2(hi.x, hi.x);  Bh[i] = pack2(-hi.y, hi.y);
        Al[i] = pack2(lo.x, lo.x);  Bl[i] = pack2(-lo.y, lo.y);
    }
#pragma unroll
    for (int r = 0; r < NR; r++) {
        u64 a = st[r];
        a = ffma2(Bh[r >> 2], swap2(a), fmul2(Ah[r >> 2], a));
        a = ffma2(Bl[r & 3],  swap2(a), fmul2(Al[r & 3],  a));
        st[r] = a;
    }
}

// ======================= batched CNOT ring (smem unit-image basis) =======================
// U = images of the 12 n-bit unit vectors under M = T0∘...∘T11 (reverse ring order).
// v0 (thread base) and the 16 per-r indices are XOR combinations (GF(2) linearity).
template<bool LAYOUT_A>
__device__ __forceinline__ void cnotx(u64* st, int t, u64* x, const unsigned* U) {
#pragma unroll
    for (int r = 0; r < NR; r++) {
        unsigned n = LAYOUT_A ? (((unsigned)t << 4) | (unsigned)r)
                              : (((unsigned)r << 8) | (unsigned)t);
        x[n + (n >> 4)] = st[r];
    }
    __syncthreads();
    // thread-bit images: LAYOUT_A -> n-bits 4..11, LAYOUT_D -> n-bits 0..7
    uint4 ua = *(const uint4*)(U + (LAYOUT_A ? 4 : 0));
    uint4 ub = *(const uint4*)(U + (LAYOUT_A ? 8 : 4));
    unsigned v0 = 0;
    if (t & 1)   v0 ^= ua.x;
    if (t & 2)   v0 ^= ua.y;
    if (t & 4)   v0 ^= ua.z;
    if (t & 8)   v0 ^= ua.w;
    if (t & 16)  v0 ^= ub.x;
    if (t & 32)  v0 ^= ub.y;
    if (t & 64)  v0 ^= ub.z;
    if (t & 128) v0 ^= ub.w;
    // reg-bit images: LAYOUT_A -> n-bits 0..3, LAYOUT_D -> n-bits 8..11
    uint4 ur = *(const uint4*)(U + (LAYOUT_A ? 0 : 8));
#pragma unroll
    for (int r = 0; r < NR; r++) {            // r compile-time -> constant-folded XOR tree
        unsigned m = v0;
        if (r & 8) m ^= ur.w;
        if (r & 4) m ^= ur.z;
        if (r & 2) m ^= ur.y;
        if (r & 1) m ^= ur.x;
        st[r] = x[m + (m >> 4)];
    }
}

// GF(2) ring transform (reverse order), used by setup threads only.
__device__ __forceinline__ unsigned ring_map(unsigned v, unsigned mask) {
#pragma unroll
    for (int k = NQ - 1; k >= 0; k--) {
        if (mask & (1u << k)) {
            const int cb = 11 - k;
            const int tb = 11 - ((k + 1) % NQ);
            v ^= ((v >> cb) & 1u) << tb;
        }
    }
    return v;
}

__device__ __forceinline__ float wred(float v) {
#pragma unroll
    for (int o = 16; o; o >>= 1) v += __shfl_xor_sync(0xFFFFFFFFu, v, o);
    return v;
}

__global__ void __launch_bounds__(NT)
qsim_kernel(const float* __restrict__ x,       // (B, 12)
            const float* __restrict__ w,       // (4, 12, 3)
            const float* __restrict__ ent,     // (4, 12)
            float* __restrict__ out)           // (B, 12)
{
    extern __shared__ __align__(16) u64 dsm[];      // 2 exchange buffers (dynamic)
    u64* x0 = dsm;                                   // sweep exchanges + warp-local
    u64* x1 = dsm + XSZ;                             // cnot permutations

    __shared__ __align__(16) u64 Usm[48 * 4];        // RY coeffs: C,S,NS,pad per gate
    __shared__ float2 Phs1[48][2];                   // RZ(phi) phases per gate per bit
    __shared__ float2 Phs2[48][2];                   // RZ(omega) phases per gate per bit
    __shared__ float red[(NT / 32) * NQ];
    __shared__ float2 encV[NQ][2];                   // encoding amps w/ layer-0 D1 folded
    __shared__ unsigned maskbits[NLAYERS];
    __shared__ __align__(16) unsigned units_sm[NLAYERS][16];  // bit images (12 used)

    const int b    = blockIdx.x;
    const int t    = threadIdx.x;
    const int lane = t & 31;
    const int wid  = t >> 5;

    // ---- precompute gates/phases/masks (parallel across threads) ----
    if (t < 64) {
        const float PI = 3.14159265358979323846f;
        if (t < NQ) {
            // encoding on wire t: column 0 of RZ(x^2 pi) RY(x pi), times layer-0 RZ(phi)
            float xv = __ldg(&x[b * NQ + t]);
            float s, c;  sincosf(0.5f * PI * xv, &s, &c);
            float sh, ch; sincosf(0.5f * PI * xv * xv, &sh, &ch);
            float2 a0 = make_float2( c * ch, -c * sh);
            float2 a1 = make_float2( s * ch,  s * sh);
            float pf = __ldg(&w[t * 3 + 0]);        // layer 0, wire t: phi
            float sp, cp; sincosf(0.5f * pf, &sp, &cp);
            encV[t][0] = cmul(a0, make_float2(cp, -sp));
            encV[t][1] = cmul(a1, make_float2(cp,  sp));
        } else if (t < 60) {
            int gi = t - NQ;   // = l*12 + q
            float phi = __ldg(&w[gi * 3 + 0]);
            float th  = __ldg(&w[gi * 3 + 1]);
            float om  = __ldg(&w[gi * 3 + 2]);
            float s, c;  sincosf(0.5f * th, &s, &c);
            u64* g = &Usm[gi * 4];
            g[0] = pack2(c, c);  g[1] = pack2(s, s);  g[2] = pack2(-s, -s);
            float sp, cp; sincosf(0.5f * phi, &sp, &cp);
            Phs1[gi][0] = make_float2(cp, -sp);
            Phs1[gi][1] = make_float2(cp,  sp);
            float so, co; sincosf(0.5f * om, &so, &co);
            Phs2[gi][0] = make_float2(co, -so);
            Phs2[gi][1] = make_float2(co,  so);
        } else {
            int l = t - 60;    // t in [60,64): build maskbits[l]
            unsigned mm = 0;
#pragma unroll
            for (int i = 0; i < NQ; i++)
                mm |= (__ldg(&ent[l * NQ + i]) > 0.5f ? 1u : 0u) << i;
            maskbits[l] = mm;
        }
    }
    __syncthreads();

    // ---- ring-perm unit images (threads 64..111); consumed after cnot barriers ----
    if (t >= 64 && t < 64 + NLAYERS * NQ) {
        int idx = t - 64, l = idx / NQ, i = idx % NQ;
        units_sm[l][i] = ring_map(1u << i, maskbits[l]);
    }

    // ---- encoded state (incl. layer-0 RZ(phi) diagonal) is a PRODUCT state ----
    // Build directly in layout D: n = (r<<8)|t; wires 0..3 = r3..r0, wires 4..11 = t7..t0.
    u64 st[NR];
    {
        float2 cm = encV[4][(t >> 7) & 1];
#pragma unroll
        for (int q = 5; q < NQ; q++)
            cm = cmul(cm, encV[q][(t >> (11 - q)) & 1]);
        float2 p01[4], p23[4];
#pragma unroll
        for (int i = 0; i < 4; i++) {
            p01[i] = cmul(encV[0][(i >> 1) & 1], encV[1][i & 1]);
            p23[i] = cmul(encV[2][(i >> 1) & 1], encV[3][i & 1]);
        }
#pragma unroll
        for (int r = 0; r < NR; r++) {
            float2 a = cmul(cmul(p01[r >> 2], p23[r & 3]), cm);
            st[r] = pack2(a.x, a.y);
        }
    }

    // ---- layers: RY sweep, D2 diag, CNOT perm, D1 diag of next layer ----
    // CTA round-trips alternate x0 (in-sweep exchange) and x1 (cnot): static schedule,
    // cnots unconditional (mask==0 -> identity perm; probability ~0).
    {
        sweep_D_to_A(st, Usm +  0 * 48, t, x0);         // layer 0 RYs
        diag_A(st, t, &Phs2[0]);                        // D2_0
        cnotx<true>(st, t, x1, units_sm[0]);
        diag_A(st, t, &Phs1[12]);                       // D1_1

        sweep_A_to_D(st, Usm +  1 * 48, t, x0);         // layer 1 RYs
        diag_D(st, t, &Phs2[12]);                       // D2_1
        cnotx<false>(st, t, x1, units_sm[1]);
        diag_D(st, t, &Phs1[24]);                       // D1_2

        sweep_D_to_A(st, Usm +  2 * 48, t, x0);         // layer 2 RYs
        diag_A(st, t, &Phs2[24]);                       // D2_2
        cnotx<true>(st, t, x1, units_sm[2]);
        diag_A(st, t, &Phs1[36]);                       // D1_3

        sweep_A_to_D(st, Usm +  3 * 48, t, x0);         // layer 3 RYs
        // D2_3 dropped: |amp|^2 is phase-invariant
        cnotx<false>(st, t, x1, units_sm[3]);
    }

    // ---- readout in layout D: wires 0..3 = r3..r0, 4..6 = warp bits, 7..11 = lane bits ----
    float psum = 0.f, a0 = 0.f, a1 = 0.f, a2 = 0.f, a3 = 0.f;
#pragma unroll
    for (int r = 0; r < NR; r++) {
        float re, im; unpack2(st[r], re, im);
        float p = fmaf(re, re, im * im);
        psum += p;
        a0 += (r & 8) ? -p : p;
        a1 += (r & 4) ? -p : p;
        a2 += (r & 2) ? -p : p;
        a3 += (r & 1) ? -p : p;
    }
    float ra0 = wred(a0), ra1 = wred(a1), ra2 = wred(a2), ra3 = wred(a3);
    float ps  = wred(psum);
    float s7  = wred((lane & 16) ? -psum : psum);
    float s8  = wred((lane &  8) ? -psum : psum);
    float s9  = wred((lane &  4) ? -psum : psum);
    float s10 = wred((lane &  2) ? -psum : psum);
    float s11 = wred((lane &  1) ? -psum : psum);
    if (lane == 0) {
        float* rw = &red[wid * NQ];
        rw[0] = ra0;  rw[1] = ra1;  rw[2] = ra2;  rw[3] = ra3;
        rw[4] = (wid & 4) ? -ps : ps;
        rw[5] = (wid & 2) ? -ps : ps;
        rw[6] = (wid & 1) ? -ps : ps;
        rw[7] = s7;  rw[8] = s8;  rw[9] = s9;  rw[10] = s10;  rw[11] = s11;
    }
    __syncthreads();

    if (t < NQ) {
        float s = 0.f;
#pragma unroll
        for (int wi = 0; wi < NT / 32; wi++) s += red[wi * NQ + t];
        out[b * NQ + t] = s;   // SCALE = 1
    }
}

extern "C" void kernel_launch(void* const* d_in, const int* in_sizes, int n_in,
                              void* d_out, int out_size)
{
    const float* x   = (const float*)d_in[0];   // (B, 12)
    const float* w   = (const float*)d_in[1];   // (4, 12, 3)
    const float* ent = (const float*)d_in[2];   // (4, 12)
    float* out = (float*)d_out;                 // (B, 12)

    const size_t shmem = 2 * XSZ * sizeof(u64);  // 69632 B dynamic
    cudaFuncSetAttribute((const void*)qsim_kernel,
                         cudaFuncAttributeMaxDynamicSharedMemorySize, (int)shmem);

    int B = in_sizes[0] / NQ;
    qsim_kernel<<<B, NT, shmem>>>(x, w, ent, out);
}